// round 8
// baseline (speedup 1.0000x reference)
#include <cuda_runtime.h>
#include <cuda_fp16.h>
#include <math.h>
#include <stdint.h>

#define NB 4
#define NT 4096
#define NS 4096
#define ND 512
#define NH 8
#define NHD 64

// Scratch (allocation-free rule: __device__ globals)
__device__ __half g_q[NB * NH * NT * NHD];
__device__ __half g_k[NB * NH * NS * NHD];
__device__ __half g_v[NB * NH * NS * NHD];
__device__ __half g_ah[3 * NB * NT * ND];   // hi split of query|key|value
__device__ __half g_al[3 * NB * NT * ND];   // lo split
__device__ __half g_wh[4 * ND * ND];        // hi split of Wq|Wk|Wv|Wo
__device__ __half g_wl[4 * ND * ND];
__device__ __half g_oh[NB * NT * ND];       // hi split of attention output
__device__ __half g_ol[NB * NT * ND];

// ===========================================================================
// helpers
// ===========================================================================
__device__ __forceinline__ float ex2f(float x) {
    float y;
    asm("ex2.approx.ftz.f32 %0, %1;" : "=f"(y) : "f"(x));
    return y;
}
__device__ __forceinline__ uint32_t packh2(float lo, float hi) {
    __half2 h = __floats2half2_rn(lo, hi);
    return *reinterpret_cast<uint32_t*>(&h);
}
__device__ __forceinline__ uint32_t cvta_s(const void* p) {
    return (uint32_t)__cvta_generic_to_shared(p);
}
// D += A * B  (m16n8k16 fp16 in, fp32 accum; A row-major, B col-major)
__device__ __forceinline__ void mma_f16(float* d, const uint32_t* a,
                                        uint32_t b0, uint32_t b1) {
    asm volatile(
        "mma.sync.aligned.m16n8k16.row.col.f32.f16.f16.f32 "
        "{%0,%1,%2,%3}, {%4,%5,%6,%7}, {%8,%9}, {%0,%1,%2,%3};"
        : "+f"(d[0]), "+f"(d[1]), "+f"(d[2]), "+f"(d[3])
        : "r"(a[0]), "r"(a[1]), "r"(a[2]), "r"(a[3]), "r"(b0), "r"(b1));
}
__device__ __forceinline__ void ldsm4(uint32_t* r, uint32_t addr) {
    asm volatile("ldmatrix.sync.aligned.m8n8.x4.shared.b16 {%0,%1,%2,%3}, [%4];"
                 : "=r"(r[0]), "=r"(r[1]), "=r"(r[2]), "=r"(r[3]) : "r"(addr));
}
__device__ __forceinline__ void ldsm4t(uint32_t* r, uint32_t addr) {
    asm volatile("ldmatrix.sync.aligned.m8n8.x4.trans.shared.b16 {%0,%1,%2,%3}, [%4];"
                 : "=r"(r[0]), "=r"(r[1]), "=r"(r[2]), "=r"(r[3]) : "r"(addr));
}
__device__ __forceinline__ void cp16(uint32_t dst, const void* src) {
    asm volatile("cp.async.cg.shared.global [%0], [%1], 16;" :: "r"(dst), "l"(src));
}
#define CP_COMMIT() asm volatile("cp.async.commit_group;")
#define CP_WAIT1()  asm volatile("cp.async.wait_group 1;")
#define CP_WAIT0()  asm volatile("cp.async.wait_group 0;")

// ---------------------------------------------------------------------------
// split: fp32 -> (hi fp16, lo fp16) with v = hi + lo + O(2^-22)
// ---------------------------------------------------------------------------
__global__ __launch_bounds__(256)
void split_kernel(const float* __restrict__ in, __half* __restrict__ hi,
                  __half* __restrict__ lo, int n)
{
    int i = (blockIdx.x * 256 + threadIdx.x) * 4;
    if (i >= n) return;
    float4 v = *(const float4*)(in + i);
    __half h[4], l[4];
    h[0] = __float2half_rn(v.x); l[0] = __float2half_rn(v.x - __half2float(h[0]));
    h[1] = __float2half_rn(v.y); l[1] = __float2half_rn(v.y - __half2float(h[1]));
    h[2] = __float2half_rn(v.z); l[2] = __float2half_rn(v.z - __half2float(h[2]));
    h[3] = __float2half_rn(v.w); l[3] = __float2half_rn(v.w - __half2float(h[3]));
    *(uint2*)(hi + i) = *(uint2*)h;
    *(uint2*)(lo + i) = *(uint2*)l;
}

// ---------------------------------------------------------------------------
// 3-term split-fp16 GEMM v2: out[M,N] = (Ah+Al)[M,512] @ (Wh+Wl)[N,512]^T + b
// keeping Ah*Wh + Ah*Wl + Al*Wh (error ~2^-22).
// CTA: 128 thr / 4 warps; tile M=128 (32 rows/warp, 2 row-frags) x N=64;
// K-step 32, cp.async double-buffered dynamic smem (61.4 KB) -> 3 CTAs/SM.
// B-fragments (W) are loaded once and shared across both row-fragments.
// head_layout=1: fp16 out to [B,H,T,64] (N-tile == head); else fp32 [M,512].
// ---------------------------------------------------------------------------
#define G2_AH 0                       // offsets in halves within a stage
#define G2_AL (128 * 40)
#define G2_WH (2 * 128 * 40)
#define G2_WL (2 * 128 * 40 + 64 * 40)
#define G2_ST (2 * 128 * 40 + 2 * 64 * 40)   // 15360 halves per stage

__global__ __launch_bounds__(128)
void gemm3_kernel(const __half* __restrict__ Ah, const __half* __restrict__ Al,
                  const __half* __restrict__ Wh, const __half* __restrict__ Wl,
                  const float* __restrict__ bias, void* __restrict__ outp,
                  int head_layout)
{
    extern __shared__ __half dsm[];

    const int tid  = threadIdx.x;
    const int warp = tid >> 5, lane = tid & 31;
    const int g = lane >> 2, q = lane & 3;
    const int m0 = blockIdx.y * 128;
    const int n0 = blockIdx.x * 64;

    const __half* Agh = Ah + (size_t)(m0 + tid) * ND;          // 1 row/thread
    const __half* Agl = Al + (size_t)(m0 + tid) * ND;
    const int wrow = tid >> 1, wc2 = (tid & 1) * 2;            // 2 chunks/thread
    const __half* Wgh = Wh + (size_t)(n0 + wrow) * ND;
    const __half* Wgl = Wl + (size_t)(n0 + wrow) * ND;

    float D[2][8][4];
#pragma unroll
    for (int rf = 0; rf < 2; rf++)
#pragma unroll
        for (int nb = 0; nb < 8; nb++)
#pragma unroll
            for (int i = 0; i < 4; i++) D[rf][nb][i] = 0.f;

    auto load_stage = [&](int stage, int k0) {
        __half* base = dsm + (stage & 1) * G2_ST;
        uint32_t ah = cvta_s(base + G2_AH + tid * 40);
        uint32_t al = cvta_s(base + G2_AL + tid * 40);
        uint32_t wh = cvta_s(base + G2_WH + wrow * 40 + wc2 * 8);
        uint32_t wl = cvta_s(base + G2_WL + wrow * 40 + wc2 * 8);
#pragma unroll
        for (int j = 0; j < 4; j++) {
            cp16(ah + j * 16, Agh + k0 + j * 8);
            cp16(al + j * 16, Agl + k0 + j * 8);
        }
#pragma unroll
        for (int j = 0; j < 2; j++) {
            cp16(wh + j * 16, Wgh + k0 + (wc2 + j) * 8);
            cp16(wl + j * 16, Wgl + k0 + (wc2 + j) * 8);
        }
        CP_COMMIT();
    };

    load_stage(0, 0);
    load_stage(1, 32);

#pragma unroll 1
    for (int it = 0; it < ND / 32; it++) {
        const __half* base = dsm + (it & 1) * G2_ST;

        if (it < ND / 32 - 1) { CP_WAIT1(); } else { CP_WAIT0(); }
        __syncthreads();

#pragma unroll
        for (int kc = 0; kc < 2; kc++) {
            uint32_t ahf[2][4], alf[2][4];
#pragma unroll
            for (int rf = 0; rf < 2; rf++) {
                int arow = warp * 32 + rf * 16 + (lane & 15);
                int acol = kc * 16 + (lane >> 4) * 8;
                ldsm4(ahf[rf], cvta_s(base + G2_AH + arow * 40 + acol));
                ldsm4(alf[rf], cvta_s(base + G2_AL + arow * 40 + acol));
            }
#pragma unroll
            for (int nbp = 0; nbp < 4; nbp++) {
                int row = nbp * 16 + ((lane >> 4) & 1) * 8 + (lane & 7);
                int col = kc * 16 + ((lane >> 3) & 1) * 8;
                uint32_t bh[4], bl[4];
                ldsm4(bh, cvta_s(base + G2_WH + row * 40 + col));
                ldsm4(bl, cvta_s(base + G2_WL + row * 40 + col));
#pragma unroll
                for (int rf = 0; rf < 2; rf++) {
                    mma_f16(D[rf][2 * nbp],     ahf[rf], bh[0], bh[1]);
                    mma_f16(D[rf][2 * nbp + 1], ahf[rf], bh[2], bh[3]);
                    mma_f16(D[rf][2 * nbp],     alf[rf], bh[0], bh[1]);
                    mma_f16(D[rf][2 * nbp + 1], alf[rf], bh[2], bh[3]);
                    mma_f16(D[rf][2 * nbp],     ahf[rf], bl[0], bl[1]);
                    mma_f16(D[rf][2 * nbp + 1], ahf[rf], bl[2], bl[3]);
                }
            }
        }
        __syncthreads();
        if (it + 2 < ND / 32) load_stage(it + 2, (it + 2) * 32);
    }

    // ---- epilogue ----
    const float* bp = bias + n0;
#pragma unroll
    for (int rf = 0; rf < 2; rf++) {
        const int mg = m0 + warp * 32 + rf * 16 + g;
#pragma unroll
        for (int nb = 0; nb < 8; nb++) {
            int c = nb * 8 + 2 * q;
            float2 bb = *(const float2*)(bp + c);
            float o00 = D[rf][nb][0] + bb.x, o01 = D[rf][nb][1] + bb.y;  // row mg
            float o10 = D[rf][nb][2] + bb.x, o11 = D[rf][nb][3] + bb.y;  // mg+8
            if (head_layout) {
                int h = n0 >> 6;
                int bbi = mg >> 12, t = mg & 4095;
                __half* oh = (__half*)outp;
                size_t bse = ((size_t)(bbi * NH + h) * NT + t) * NHD + c;
                *(__half2*)&oh[bse]           = __floats2half2_rn(o00, o01);
                *(__half2*)&oh[bse + 8 * NHD] = __floats2half2_rn(o10, o11);
            } else {
                float* of = (float*)outp;
                size_t bse = (size_t)mg * ND + n0 + c;
                *(float2*)&of[bse]          = make_float2(o00, o01);
                *(float2*)&of[bse + 8 * ND] = make_float2(o10, o11);
            }
        }
    }
}

// ---------------------------------------------------------------------------
// fp16 flash attention v5: 2 warps/CTA, 32 T-rows/warp (2 row-fragments
// sharing every K/V B-fragment), cp.async double-buffered K/V, P in regs,
// row sums via P@ones MMA, skip-rescale, mask fast path.
// Emits hi/lo fp16 split of the output for the Wo GEMM.
// ---------------------------------------------------------------------------
__global__ __launch_bounds__(64)
void attn_kernel(const __half* __restrict__ Qh, const __half* __restrict__ Kh,
                 const __half* __restrict__ Vh,
                 const unsigned char* __restrict__ mask,
                 __half* __restrict__ outh, __half* __restrict__ outl)
{
    __shared__ __half Ksh[2][64][72];   // K tile [s][d], double-buffered
    __shared__ __half Vsh[2][64][72];   // V tile [s][d], double-buffered
    __shared__ uint32_t MskW[2][16];    // 64 mask bytes / buffer

    const int b  = blockIdx.z;
    const int h  = blockIdx.y;
    const int t0 = blockIdx.x * 64;
    const int tid  = threadIdx.x;
    const int warp = tid >> 5;
    const int lane = tid & 31;
    const int g = lane >> 2;
    const int q = lane & 3;
    const int w32 = warp * 32;
    const uint32_t ONES = 0x3C003C00u;   // half2(1,1)

    const __half* Kp = Kh + (size_t)(b * NH + h) * NS * NHD;
    const __half* Vp = Vh + (size_t)(b * NH + h) * NS * NHD;
    const unsigned char* mp = mask + (size_t)b * NS;

    // ---- Q fragments (fp16 regs, once), scale 0.125*log2(e) ----
    uint32_t Qf[2][4][4];
    {
        const __half2 qs2 = __float2half2_rn(0.125f * 1.4426950408889634f);
#pragma unroll
        for (int rf = 0; rf < 2; rf++) {
            const __half* Q0 = Qh + ((size_t)(b * NH + h) * NT
                                     + t0 + w32 + rf * 16 + g) * NHD;
            const __half* Q1 = Q0 + 8 * NHD;
#pragma unroll
            for (int kc = 0; kc < 4; kc++) {
                __half2 x0 = __hmul2(*(const __half2*)(Q0 + kc * 16 + 2 * q),     qs2);
                __half2 x1 = __hmul2(*(const __half2*)(Q1 + kc * 16 + 2 * q),     qs2);
                __half2 x2 = __hmul2(*(const __half2*)(Q0 + kc * 16 + 2 * q + 8), qs2);
                __half2 x3 = __hmul2(*(const __half2*)(Q1 + kc * 16 + 2 * q + 8), qs2);
                Qf[rf][kc][0] = *(uint32_t*)&x0;
                Qf[rf][kc][1] = *(uint32_t*)&x1;
                Qf[rf][kc][2] = *(uint32_t*)&x2;
                Qf[rf][kc][3] = *(uint32_t*)&x3;
            }
        }
    }

    float O[2][8][4];
#pragma unroll
    for (int rf = 0; rf < 2; rf++)
#pragma unroll
        for (int nb = 0; nb < 8; nb++)
#pragma unroll
            for (int i = 0; i < 4; i++) O[rf][nb][i] = 0.f;
    float mrow[4] = {-INFINITY, -INFINITY, -INFINITY, -INFINITY};
    float lrow[4] = {0.f, 0.f, 0.f, 0.f};

    // ---- prologue: async-load tiles 0 and 1 (1 K-row + 1 V-row per thread) --
#pragma unroll
    for (int t = 0; t < 2; t++) {
        const __half* kg = Kp + (size_t)(t * 64 + tid) * NHD;
        const __half* vg = Vp + (size_t)(t * 64 + tid) * NHD;
        uint32_t kd = cvta_s(&Ksh[t][tid][0]);
        uint32_t vd = cvta_s(&Vsh[t][tid][0]);
#pragma unroll
        for (int j = 0; j < 8; j++) {
            cp16(kd + j * 16, kg + j * 8);
            cp16(vd + j * 16, vg + j * 8);
        }
        if (tid < 4) cp16(cvta_s(&MskW[t][tid * 4]), mp + t * 64 + tid * 16);
        CP_COMMIT();
    }

#pragma unroll 1
    for (int it = 0; it < NS / 64; it++) {
        const int cur = it & 1;
        if (it < NS / 64 - 1) { CP_WAIT1(); } else { CP_WAIT0(); }
        int any = __syncthreads_or((tid < 16) ? (int)(MskW[cur][tid] != 0u) : 0);

        // ---- QK^T: B-frags loaded once, shared by both row-fragments ----
        float D[2][8][4];
#pragma unroll
        for (int rf = 0; rf < 2; rf++)
#pragma unroll
            for (int nb = 0; nb < 8; nb++) {
                D[rf][nb][0] = 0.f; D[rf][nb][1] = 0.f;
                D[rf][nb][2] = 0.f; D[rf][nb][3] = 0.f;
            }
#pragma unroll
        for (int kc = 0; kc < 4; kc++) {
#pragma unroll
            for (int nbp = 0; nbp < 4; nbp++) {
                int row = nbp * 16 + ((lane >> 4) & 1) * 8 + (lane & 7);
                int col = kc * 16 + ((lane >> 3) & 1) * 8;
                uint32_t bf[4];
                ldsm4(bf, cvta_s(&Ksh[cur][row][col]));
#pragma unroll
                for (int rf = 0; rf < 2; rf++) {
                    mma_f16(D[rf][2 * nbp],     Qf[rf][kc], bf[0], bf[1]);
                    mma_f16(D[rf][2 * nbp + 1], Qf[rf][kc], bf[2], bf[3]);
                }
            }
        }

        // ---- mask (fast path skips when tile unmasked) ----
        if (any) {
            const unsigned char* Msk = (const unsigned char*)&MskW[cur][0];
#pragma unroll
            for (int nb = 0; nb < 8; nb++) {
                int c0 = nb * 8 + 2 * q;
                unsigned char k0 = Msk[c0], k1 = Msk[c0 + 1];
#pragma unroll
                for (int rf = 0; rf < 2; rf++) {
                    if (k0) { D[rf][nb][0] = -INFINITY; D[rf][nb][2] = -INFINITY; }
                    if (k1) { D[rf][nb][1] = -INFINITY; D[rf][nb][3] = -INFINITY; }
                }
            }
        }

        // ---- online softmax (log2 domain); 4 rows per thread ----
        float ml[4] = {-INFINITY, -INFINITY, -INFINITY, -INFINITY};
#pragma unroll
        for (int rf = 0; rf < 2; rf++)
#pragma unroll
            for (int nb = 0; nb < 8; nb++) {
                ml[2 * rf]     = fmaxf(ml[2 * rf],     fmaxf(D[rf][nb][0], D[rf][nb][1]));
                ml[2 * rf + 1] = fmaxf(ml[2 * rf + 1], fmaxf(D[rf][nb][2], D[rf][nb][3]));
            }
#pragma unroll
        for (int i = 0; i < 4; i++) {
            ml[i] = fmaxf(ml[i], __shfl_xor_sync(0xffffffffu, ml[i], 1));
            ml[i] = fmaxf(ml[i], __shfl_xor_sync(0xffffffffu, ml[i], 2));
        }

        float ms[4], f[4];
        bool moved = false;
#pragma unroll
        for (int i = 0; i < 4; i++) {
            float mn = fmaxf(mrow[i], ml[i]);
            moved |= (ml[i] > mrow[i]);
            ms[i] = (mn == -INFINITY) ? 0.f : mn;
            f[i]  = ex2f(mrow[i] - ms[i]);   // exactly 1.0 if max unchanged
            mrow[i] = mn;
        }
#pragma unroll
        for (int rf = 0; rf < 2; rf++)
#pragma unroll
            for (int nb = 0; nb < 8; nb++) {
                D[rf][nb][0] = ex2f(D[rf][nb][0] - ms[2 * rf]);
                D[rf][nb][1] = ex2f(D[rf][nb][1] - ms[2 * rf]);
                D[rf][nb][2] = ex2f(D[rf][nb][2] - ms[2 * rf + 1]);
                D[rf][nb][3] = ex2f(D[rf][nb][3] - ms[2 * rf + 1]);
            }
        if (moved) {
#pragma unroll
            for (int rf = 0; rf < 2; rf++)
#pragma unroll
                for (int nb = 0; nb < 8; nb++) {
                    O[rf][nb][0] *= f[2 * rf];     O[rf][nb][1] *= f[2 * rf];
                    O[rf][nb][2] *= f[2 * rf + 1]; O[rf][nb][3] *= f[2 * rf + 1];
                }
        }

        // ---- O += P @ V ; row sums via P @ ones ----
        float Ssum[2][4] = {{0.f, 0.f, 0.f, 0.f}, {0.f, 0.f, 0.f, 0.f}};
#pragma unroll
        for (int kk = 0; kk < 4; kk++) {
            uint32_t a[2][4];
#pragma unroll
            for (int rf = 0; rf < 2; rf++) {
                a[rf][0] = packh2(D[rf][2 * kk][0],     D[rf][2 * kk][1]);
                a[rf][1] = packh2(D[rf][2 * kk][2],     D[rf][2 * kk][3]);
                a[rf][2] = packh2(D[rf][2 * kk + 1][0], D[rf][2 * kk + 1][1]);
                a[rf][3] = packh2(D[rf][2 * kk + 1][2], D[rf][2 * kk + 1][3]);
                mma_f16(Ssum[rf], a[rf], ONES, ONES);
            }
#pragma unroll
            for (int nbp = 0; nbp < 4; nbp++) {
                int row = kk * 16 + ((lane >> 3) & 1) * 8 + (lane & 7);
                int col = nbp * 16 + ((lane >> 4) & 1) * 8;
                uint32_t bf[4];
                ldsm4t(bf, cvta_s(&Vsh[cur][row][col]));
#pragma unroll
                for (int rf = 0; rf < 2; rf++) {
                    mma_f16(O[rf][2 * nbp],     a[rf], bf[0], bf[1]);
                    mma_f16(O[rf][2 * nbp + 1], a[rf], bf[2], bf[3]);
                }
            }
        }
#pragma unroll
        for (int rf = 0; rf < 2; rf++) {
            lrow[2 * rf]     = lrow[2 * rf]     * f[2 * rf]     + Ssum[rf][0];
            lrow[2 * rf + 1] = lrow[2 * rf + 1] * f[2 * rf + 1] + Ssum[rf][2];
        }

        __syncthreads();   // all reads of buf `cur` done
        if (it + 2 < NS / 64) {
            int s0n = (it + 2) * 64;
            const __half* kg = Kp + (size_t)(s0n + tid) * NHD;
            const __half* vg = Vp + (size_t)(s0n + tid) * NHD;
            uint32_t kd = cvta_s(&Ksh[cur][tid][0]);
            uint32_t vd = cvta_s(&Vsh[cur][tid][0]);
#pragma unroll
            for (int j = 0; j < 8; j++) {
                cp16(kd + j * 16, kg + j * 8);
                cp16(vd + j * 16, vg + j * 8);
            }
            if (tid < 4) cp16(cvta_s(&MskW[cur][tid * 4]), mp + s0n + tid * 16);
            CP_COMMIT();
        }
    }

    // ---- epilogue: normalize, emit hi/lo fp16 split at [B*T, D] ----
#pragma unroll
    for (int rf = 0; rf < 2; rf++) {
        float inv0 = (lrow[2 * rf]     > 0.f) ? (1.0f / lrow[2 * rf])     : 0.f;
        float inv1 = (lrow[2 * rf + 1] > 0.f) ? (1.0f / lrow[2 * rf + 1]) : 0.f;
        size_t r0 = ((size_t)(b * NT + t0 + w32 + rf * 16 + g))     * ND + h * NHD;
        size_t r1 = ((size_t)(b * NT + t0 + w32 + rf * 16 + g + 8)) * ND + h * NHD;
#pragma unroll
        for (int nb = 0; nb < 8; nb++) {
            int c = nb * 8 + 2 * q;
            float x0 = O[rf][nb][0] * inv0, x1 = O[rf][nb][1] * inv0;
            float x2 = O[rf][nb][2] * inv1, x3 = O[rf][nb][3] * inv1;
            __half h0 = __float2half_rn(x0), h1 = __float2half_rn(x1);
            __half h2 = __float2half_rn(x2), h3 = __float2half_rn(x3);
            *(__half2*)&outh[r0 + c] = __halves2half2(h0, h1);
            *(__half2*)&outh[r1 + c] = __halves2half2(h2, h3);
            *(__half2*)&outl[r0 + c] = __floats2half2_rn(
                x0 - __half2float(h0), x1 - __half2float(h1));
            *(__half2*)&outl[r1 + c] = __floats2half2_rn(
                x2 - __half2float(h2), x3 - __half2float(h3));
        }
    }
}

// ---------------------------------------------------------------------------
extern "C" void kernel_launch(void* const* d_in, const int* in_sizes, int n_in,
                              void* d_out, int out_size)
{
    const float* query = (const float*)d_in[0];
    const float* key   = (const float*)d_in[1];
    const float* value = (const float*)d_in[2];
    const unsigned char* mask = (const unsigned char*)d_in[3];
    const float* Wq = (const float*)d_in[4];
    const float* bq = (const float*)d_in[5];
    const float* Wk = (const float*)d_in[6];
    const float* bk = (const float*)d_in[7];
    const float* Wv = (const float*)d_in[8];
    const float* bv = (const float*)d_in[9];
    const float* Wo = (const float*)d_in[10];
    const float* bo = (const float*)d_in[11];
    float* out = (float*)d_out;

    __half *qb, *kb, *vb, *ah, *al, *wh, *wl, *oh, *ol;
    cudaGetSymbolAddress((void**)&qb, g_q);
    cudaGetSymbolAddress((void**)&kb, g_k);
    cudaGetSymbolAddress((void**)&vb, g_v);
    cudaGetSymbolAddress((void**)&ah, g_ah);
    cudaGetSymbolAddress((void**)&al, g_al);
    cudaGetSymbolAddress((void**)&wh, g_wh);
    cudaGetSymbolAddress((void**)&wl, g_wl);
    cudaGetSymbolAddress((void**)&oh, g_oh);
    cudaGetSymbolAddress((void**)&ol, g_ol);

    const int smem3 = G2_ST * 2 * (int)sizeof(__half);   // 61440 B
    cudaFuncSetAttribute(gemm3_kernel,
                         cudaFuncAttributeMaxDynamicSharedMemorySize, smem3);

    const int NW = ND * ND;               // 262144 per weight
    const int NA = NB * NT * ND;          // 8388608 per activation

    split_kernel<<<NW / 1024, 256>>>(Wq, wh + 0 * NW, wl + 0 * NW, NW);
    split_kernel<<<NW / 1024, 256>>>(Wk, wh + 1 * NW, wl + 1 * NW, NW);
    split_kernel<<<NW / 1024, 256>>>(Wv, wh + 2 * NW, wl + 2 * NW, NW);
    split_kernel<<<NW / 1024, 256>>>(Wo, wh + 3 * NW, wl + 3 * NW, NW);
    split_kernel<<<NA / 1024, 256>>>(query, ah + 0L * NA, al + 0L * NA, NA);
    split_kernel<<<NA / 1024, 256>>>(key,   ah + 1L * NA, al + 1L * NA, NA);
    split_kernel<<<NA / 1024, 256>>>(value, ah + 2L * NA, al + 2L * NA, NA);

    dim3 gg(ND / 64, (NB * NT) / 128);    // (8, 128)
    gemm3_kernel<<<gg, 128, smem3>>>(ah + 0L * NA, al + 0L * NA,
                                     wh + 0 * NW, wl + 0 * NW, bq, qb, 1);
    gemm3_kernel<<<gg, 128, smem3>>>(ah + 1L * NA, al + 1L * NA,
                                     wh + 1 * NW, wl + 1 * NW, bk, kb, 1);
    gemm3_kernel<<<gg, 128, smem3>>>(ah + 2L * NA, al + 2L * NA,
                                     wh + 2 * NW, wl + 2 * NW, bv, vb, 1);

    dim3 ga(NT / 64, NH, NB);             // (64, 8, 4)
    attn_kernel<<<ga, 64>>>(qb, kb, vb, mask, oh, ol);

    gemm3_kernel<<<gg, 128, smem3>>>(oh, ol, wh + 3 * NW, wl + 3 * NW,
                                     bo, out, 0);
}

// round 9
// speedup vs baseline: 1.0728x; 1.0728x over previous
#include <cuda_runtime.h>
#include <cuda_fp16.h>
#include <math.h>
#include <stdint.h>

#define NB 4
#define NT 4096
#define NS 4096
#define ND 512
#define NH 8
#define NHD 64

// Scratch (allocation-free rule: __device__ globals)
__device__ __half g_q[NB * NH * NT * NHD];
__device__ __half g_k[NB * NH * NS * NHD];
__device__ __half g_v[NB * NH * NS * NHD];
__device__ __half g_ah[3 * NB * NT * ND];   // hi split of query|key|value
__device__ __half g_al[3 * NB * NT * ND];   // lo split
__device__ __half g_wh[4 * ND * ND];        // hi split of Wq|Wk|Wv|Wo
__device__ __half g_wl[4 * ND * ND];
__device__ __half g_oh[NB * NT * ND];       // hi split of attention output
__device__ __half g_ol[NB * NT * ND];

// ===========================================================================
// helpers
// ===========================================================================
__device__ __forceinline__ float ex2f(float x) {
    float y;
    asm("ex2.approx.ftz.f32 %0, %1;" : "=f"(y) : "f"(x));
    return y;
}
__device__ __forceinline__ uint32_t packh2(float lo, float hi) {
    __half2 h = __floats2half2_rn(lo, hi);
    return *reinterpret_cast<uint32_t*>(&h);
}
__device__ __forceinline__ uint32_t cvta_s(const void* p) {
    return (uint32_t)__cvta_generic_to_shared(p);
}
// D += A * B  (m16n8k16 fp16 in, fp32 accum; A row-major, B col-major)
__device__ __forceinline__ void mma_f16(float* d, const uint32_t* a,
                                        uint32_t b0, uint32_t b1) {
    asm volatile(
        "mma.sync.aligned.m16n8k16.row.col.f32.f16.f16.f32 "
        "{%0,%1,%2,%3}, {%4,%5,%6,%7}, {%8,%9}, {%0,%1,%2,%3};"
        : "+f"(d[0]), "+f"(d[1]), "+f"(d[2]), "+f"(d[3])
        : "r"(a[0]), "r"(a[1]), "r"(a[2]), "r"(a[3]), "r"(b0), "r"(b1));
}
__device__ __forceinline__ void ldsm4(uint32_t* r, uint32_t addr) {
    asm volatile("ldmatrix.sync.aligned.m8n8.x4.shared.b16 {%0,%1,%2,%3}, [%4];"
                 : "=r"(r[0]), "=r"(r[1]), "=r"(r[2]), "=r"(r[3]) : "r"(addr));
}
__device__ __forceinline__ void ldsm4t(uint32_t* r, uint32_t addr) {
    asm volatile("ldmatrix.sync.aligned.m8n8.x4.trans.shared.b16 {%0,%1,%2,%3}, [%4];"
                 : "=r"(r[0]), "=r"(r[1]), "=r"(r[2]), "=r"(r[3]) : "r"(addr));
}
__device__ __forceinline__ void cp16(uint32_t dst, const void* src) {
    asm volatile("cp.async.cg.shared.global [%0], [%1], 16;" :: "r"(dst), "l"(src));
}
#define CP_COMMIT() asm volatile("cp.async.commit_group;")
#define CP_WAIT1()  asm volatile("cp.async.wait_group 1;")
#define CP_WAIT0()  asm volatile("cp.async.wait_group 0;")

// ---------------------------------------------------------------------------
// split: fp32 -> (hi fp16, lo fp16) with v = hi + lo + O(2^-22)
// ---------------------------------------------------------------------------
__global__ __launch_bounds__(256)
void split_kernel(const float* __restrict__ in, __half* __restrict__ hi,
                  __half* __restrict__ lo, int n)
{
    int i = (blockIdx.x * 256 + threadIdx.x) * 4;
    if (i >= n) return;
    float4 v = *(const float4*)(in + i);
    __half h[4], l[4];
    h[0] = __float2half_rn(v.x); l[0] = __float2half_rn(v.x - __half2float(h[0]));
    h[1] = __float2half_rn(v.y); l[1] = __float2half_rn(v.y - __half2float(h[1]));
    h[2] = __float2half_rn(v.z); l[2] = __float2half_rn(v.z - __half2float(h[2]));
    h[3] = __float2half_rn(v.w); l[3] = __float2half_rn(v.w - __half2float(h[3]));
    *(uint2*)(hi + i) = *(uint2*)h;
    *(uint2*)(lo + i) = *(uint2*)l;
}

// ---------------------------------------------------------------------------
// 3-term split-fp16 GEMM v2 (R8): out = (Ah+Al) @ (Wh+Wl)^T + b, keeping
// Ah*Wh + Ah*Wl + Al*Wh. CTA: 128 thr / 4 warps; M=128 (32 rows/warp,
// 2 row-frags) x N=64; K-step 32; double-buffered 61.4 KB -> 3 CTAs/SM.
// ---------------------------------------------------------------------------
#define G2_AH 0                       // offsets in halves within a stage
#define G2_AL (128 * 40)
#define G2_WH (2 * 128 * 40)
#define G2_WL (2 * 128 * 40 + 64 * 40)
#define G2_ST (2 * 128 * 40 + 2 * 64 * 40)   // 15360 halves per stage

__global__ __launch_bounds__(128)
void gemm3_kernel(const __half* __restrict__ Ah, const __half* __restrict__ Al,
                  const __half* __restrict__ Wh, const __half* __restrict__ Wl,
                  const float* __restrict__ bias, void* __restrict__ outp,
                  int head_layout)
{
    extern __shared__ __half dsm[];

    const int tid  = threadIdx.x;
    const int warp = tid >> 5, lane = tid & 31;
    const int g = lane >> 2, q = lane & 3;
    const int m0 = blockIdx.y * 128;
    const int n0 = blockIdx.x * 64;

    const __half* Agh = Ah + (size_t)(m0 + tid) * ND;          // 1 row/thread
    const __half* Agl = Al + (size_t)(m0 + tid) * ND;
    const int wrow = tid >> 1, wc2 = (tid & 1) * 2;            // 2 chunks/thread
    const __half* Wgh = Wh + (size_t)(n0 + wrow) * ND;
    const __half* Wgl = Wl + (size_t)(n0 + wrow) * ND;

    float D[2][8][4];
#pragma unroll
    for (int rf = 0; rf < 2; rf++)
#pragma unroll
        for (int nb = 0; nb < 8; nb++)
#pragma unroll
            for (int i = 0; i < 4; i++) D[rf][nb][i] = 0.f;

    auto load_stage = [&](int stage, int k0) {
        __half* base = dsm + (stage & 1) * G2_ST;
        uint32_t ah = cvta_s(base + G2_AH + tid * 40);
        uint32_t al = cvta_s(base + G2_AL + tid * 40);
        uint32_t wh = cvta_s(base + G2_WH + wrow * 40 + wc2 * 8);
        uint32_t wl = cvta_s(base + G2_WL + wrow * 40 + wc2 * 8);
#pragma unroll
        for (int j = 0; j < 4; j++) {
            cp16(ah + j * 16, Agh + k0 + j * 8);
            cp16(al + j * 16, Agl + k0 + j * 8);
        }
#pragma unroll
        for (int j = 0; j < 2; j++) {
            cp16(wh + j * 16, Wgh + k0 + (wc2 + j) * 8);
            cp16(wl + j * 16, Wgl + k0 + (wc2 + j) * 8);
        }
        CP_COMMIT();
    };

    load_stage(0, 0);
    load_stage(1, 32);

#pragma unroll 1
    for (int it = 0; it < ND / 32; it++) {
        const __half* base = dsm + (it & 1) * G2_ST;

        if (it < ND / 32 - 1) { CP_WAIT1(); } else { CP_WAIT0(); }
        __syncthreads();

#pragma unroll
        for (int kc = 0; kc < 2; kc++) {
            uint32_t ahf[2][4], alf[2][4];
#pragma unroll
            for (int rf = 0; rf < 2; rf++) {
                int arow = warp * 32 + rf * 16 + (lane & 15);
                int acol = kc * 16 + (lane >> 4) * 8;
                ldsm4(ahf[rf], cvta_s(base + G2_AH + arow * 40 + acol));
                ldsm4(alf[rf], cvta_s(base + G2_AL + arow * 40 + acol));
            }
#pragma unroll
            for (int nbp = 0; nbp < 4; nbp++) {
                int row = nbp * 16 + ((lane >> 4) & 1) * 8 + (lane & 7);
                int col = kc * 16 + ((lane >> 3) & 1) * 8;
                uint32_t bh[4], bl[4];
                ldsm4(bh, cvta_s(base + G2_WH + row * 40 + col));
                ldsm4(bl, cvta_s(base + G2_WL + row * 40 + col));
#pragma unroll
                for (int rf = 0; rf < 2; rf++) {
                    mma_f16(D[rf][2 * nbp],     ahf[rf], bh[0], bh[1]);
                    mma_f16(D[rf][2 * nbp + 1], ahf[rf], bh[2], bh[3]);
                    mma_f16(D[rf][2 * nbp],     alf[rf], bh[0], bh[1]);
                    mma_f16(D[rf][2 * nbp + 1], alf[rf], bh[2], bh[3]);
                    mma_f16(D[rf][2 * nbp],     ahf[rf], bl[0], bl[1]);
                    mma_f16(D[rf][2 * nbp + 1], ahf[rf], bl[2], bl[3]);
                }
            }
        }
        __syncthreads();
        if (it + 2 < ND / 32) load_stage(it + 2, (it + 2) * 32);
    }

    // ---- epilogue ----
    const float* bp = bias + n0;
#pragma unroll
    for (int rf = 0; rf < 2; rf++) {
        const int mg = m0 + warp * 32 + rf * 16 + g;
#pragma unroll
        for (int nb = 0; nb < 8; nb++) {
            int c = nb * 8 + 2 * q;
            float2 bb = *(const float2*)(bp + c);
            float o00 = D[rf][nb][0] + bb.x, o01 = D[rf][nb][1] + bb.y;  // row mg
            float o10 = D[rf][nb][2] + bb.x, o11 = D[rf][nb][3] + bb.y;  // mg+8
            if (head_layout) {
                int h = n0 >> 6;
                int bbi = mg >> 12, t = mg & 4095;
                __half* oh = (__half*)outp;
                size_t bse = ((size_t)(bbi * NH + h) * NT + t) * NHD + c;
                *(__half2*)&oh[bse]           = __floats2half2_rn(o00, o01);
                *(__half2*)&oh[bse + 8 * NHD] = __floats2half2_rn(o10, o11);
            } else {
                float* of = (float*)outp;
                size_t bse = (size_t)mg * ND + n0 + c;
                *(float2*)&of[bse]          = make_float2(o00, o01);
                *(float2*)&of[bse + 8 * ND] = make_float2(o10, o11);
            }
        }
    }
}

// ---------------------------------------------------------------------------
// fp16 flash attention v4 (R7, proven 609us): 4 warps/CTA, 16 rows/warp,
// cp.async double-buffered K/V, ldmatrix frags, P in regs, row sums via
// P@ones MMA, skip-rescale, mask fast path. Emits hi/lo fp16 output split.
// ---------------------------------------------------------------------------
__global__ __launch_bounds__(128)
void attn_kernel(const __half* __restrict__ Qh, const __half* __restrict__ Kh,
                 const __half* __restrict__ Vh,
                 const unsigned char* __restrict__ mask,
                 __half* __restrict__ outh, __half* __restrict__ outl)
{
    __shared__ __half Ksh[2][64][72];   // K tile [s][d], double-buffered
    __shared__ __half Vsh[2][64][72];   // V tile [s][d], double-buffered
    __shared__ uint32_t MskW[2][16];    // 64 mask bytes / buffer

    const int b  = blockIdx.z;
    const int h  = blockIdx.y;
    const int t0 = blockIdx.x * 64;
    const int tid  = threadIdx.x;
    const int warp = tid >> 5;
    const int lane = tid & 31;
    const int g = lane >> 2;
    const int q = lane & 3;
    const int w16 = warp * 16;
    const uint32_t ONES = 0x3C003C00u;   // half2(1,1)

    const __half* Kp = Kh + (size_t)(b * NH + h) * NS * NHD;
    const __half* Vp = Vh + (size_t)(b * NH + h) * NS * NHD;
    const unsigned char* mp = mask + (size_t)b * NS;

    const int lrow = tid >> 1;
    const int lcol = (tid & 1) * 32;

    // ---- Q fragments (fp16 regs, once), scale 0.125*log2(e) ----
    uint32_t Qf[4][4];
    {
        const __half2 qs2 = __float2half2_rn(0.125f * 1.4426950408889634f);
        const __half* Q0 = Qh + ((size_t)(b * NH + h) * NT + t0 + w16 + g) * NHD;
        const __half* Q1 = Q0 + 8 * NHD;
#pragma unroll
        for (int kc = 0; kc < 4; kc++) {
            __half2 x0 = __hmul2(*(const __half2*)(Q0 + kc * 16 + 2 * q),     qs2);
            __half2 x1 = __hmul2(*(const __half2*)(Q1 + kc * 16 + 2 * q),     qs2);
            __half2 x2 = __hmul2(*(const __half2*)(Q0 + kc * 16 + 2 * q + 8), qs2);
            __half2 x3 = __hmul2(*(const __half2*)(Q1 + kc * 16 + 2 * q + 8), qs2);
            Qf[kc][0] = *(uint32_t*)&x0;
            Qf[kc][1] = *(uint32_t*)&x1;
            Qf[kc][2] = *(uint32_t*)&x2;
            Qf[kc][3] = *(uint32_t*)&x3;
        }
    }

    float O[8][4];
#pragma unroll
    for (int nb = 0; nb < 8; nb++)
#pragma unroll
        for (int i = 0; i < 4; i++) O[nb][i] = 0.f;
    float m0 = -INFINITY, m1 = -INFINITY, l0 = 0.f, l1 = 0.f;

    // ---- prologue: async-load tiles 0 and 1 ----
#pragma unroll
    for (int t = 0; t < 2; t++) {
        const __half* kg = Kp + (size_t)(t * 64 + lrow) * NHD + lcol;
        const __half* vg = Vp + (size_t)(t * 64 + lrow) * NHD + lcol;
        uint32_t kd = cvta_s(&Ksh[t][lrow][lcol]);
        uint32_t vd = cvta_s(&Vsh[t][lrow][lcol]);
#pragma unroll
        for (int j = 0; j < 4; j++) {
            cp16(kd + j * 16, kg + j * 8);
            cp16(vd + j * 16, vg + j * 8);
        }
        if (tid < 4) cp16(cvta_s(&MskW[t][tid * 4]), mp + t * 64 + tid * 16);
        CP_COMMIT();
    }

#pragma unroll 1
    for (int it = 0; it < NS / 64; it++) {
        const int cur = it & 1;
        if (it < NS / 64 - 1) { CP_WAIT1(); } else { CP_WAIT0(); }
        int any = __syncthreads_or((tid < 16) ? (int)(MskW[cur][tid] != 0u) : 0);

        // ---- QK^T via ldmatrix(non-trans) B-frags ----
        float D[8][4];
#pragma unroll
        for (int nb = 0; nb < 8; nb++) {
            D[nb][0] = 0.f; D[nb][1] = 0.f; D[nb][2] = 0.f; D[nb][3] = 0.f;
        }
#pragma unroll
        for (int kc = 0; kc < 4; kc++) {
#pragma unroll
            for (int nbp = 0; nbp < 4; nbp++) {
                int row = nbp * 16 + ((lane >> 4) & 1) * 8 + (lane & 7);
                int col = kc * 16 + ((lane >> 3) & 1) * 8;
                uint32_t bf[4];
                ldsm4(bf, cvta_s(&Ksh[cur][row][col]));
                mma_f16(D[2 * nbp],     Qf[kc], bf[0], bf[1]);
                mma_f16(D[2 * nbp + 1], Qf[kc], bf[2], bf[3]);
            }
        }

        // ---- mask (fast path skips when tile unmasked) ----
        if (any) {
            const unsigned char* Msk = (const unsigned char*)&MskW[cur][0];
#pragma unroll
            for (int nb = 0; nb < 8; nb++) {
                int c0 = nb * 8 + 2 * q;
                if (Msk[c0])     { D[nb][0] = -INFINITY; D[nb][2] = -INFINITY; }
                if (Msk[c0 + 1]) { D[nb][1] = -INFINITY; D[nb][3] = -INFINITY; }
            }
        }

        // ---- online softmax (log2 domain); rows g, g+8 ----
        float ml0 = -INFINITY, ml1 = -INFINITY;
#pragma unroll
        for (int nb = 0; nb < 8; nb++) {
            ml0 = fmaxf(ml0, fmaxf(D[nb][0], D[nb][1]));
            ml1 = fmaxf(ml1, fmaxf(D[nb][2], D[nb][3]));
        }
        ml0 = fmaxf(ml0, __shfl_xor_sync(0xffffffffu, ml0, 1));
        ml0 = fmaxf(ml0, __shfl_xor_sync(0xffffffffu, ml0, 2));
        ml1 = fmaxf(ml1, __shfl_xor_sync(0xffffffffu, ml1, 1));
        ml1 = fmaxf(ml1, __shfl_xor_sync(0xffffffffu, ml1, 2));

        float mn0 = fmaxf(m0, ml0), mn1 = fmaxf(m1, ml1);
        float ms0 = (mn0 == -INFINITY) ? 0.f : mn0;
        float ms1 = (mn1 == -INFINITY) ? 0.f : mn1;
#pragma unroll
        for (int nb = 0; nb < 8; nb++) {
            D[nb][0] = ex2f(D[nb][0] - ms0);
            D[nb][1] = ex2f(D[nb][1] - ms0);
            D[nb][2] = ex2f(D[nb][2] - ms1);
            D[nb][3] = ex2f(D[nb][3] - ms1);
        }

        float f0 = ex2f(m0 - ms0);   // exact 1.0 when max unchanged
        float f1 = ex2f(m1 - ms1);
        if (ml0 > m0 || ml1 > m1) {  // rescale only when a max moved
#pragma unroll
            for (int nb = 0; nb < 8; nb++) {
                O[nb][0] *= f0; O[nb][1] *= f0;
                O[nb][2] *= f1; O[nb][3] *= f1;
            }
        }
        m0 = mn0; m1 = mn1;

        // ---- O += P @ V ; row sums via P @ ones ----
        float Ssum[4] = {0.f, 0.f, 0.f, 0.f};
#pragma unroll
        for (int kk = 0; kk < 4; kk++) {
            uint32_t a[4];
            a[0] = packh2(D[2 * kk][0],     D[2 * kk][1]);
            a[1] = packh2(D[2 * kk][2],     D[2 * kk][3]);
            a[2] = packh2(D[2 * kk + 1][0], D[2 * kk + 1][1]);
            a[3] = packh2(D[2 * kk + 1][2], D[2 * kk + 1][3]);
            mma_f16(Ssum, a, ONES, ONES);
#pragma unroll
            for (int nbp = 0; nbp < 4; nbp++) {
                int row = kk * 16 + ((lane >> 3) & 1) * 8 + (lane & 7);
                int col = nbp * 16 + ((lane >> 4) & 1) * 8;
                uint32_t bf[4];
                ldsm4t(bf, cvta_s(&Vsh[cur][row][col]));
                mma_f16(O[2 * nbp],     a, bf[0], bf[1]);
                mma_f16(O[2 * nbp + 1], a, bf[2], bf[3]);
            }
        }
        l0 = l0 * f0 + Ssum[0];
        l1 = l1 * f1 + Ssum[2];

        __syncthreads();   // all reads of buf `cur` done
        if (it + 2 < NS / 64) {
            int s0n = (it + 2) * 64;
            const __half* kg = Kp + (size_t)(s0n + lrow) * NHD + lcol;
            const __half* vg = Vp + (size_t)(s0n + lrow) * NHD + lcol;
            uint32_t kd = cvta_s(&Ksh[cur][lrow][lcol]);
            uint32_t vd = cvta_s(&Vsh[cur][lrow][lcol]);
#pragma unroll
            for (int j = 0; j < 4; j++) {
                cp16(kd + j * 16, kg + j * 8);
                cp16(vd + j * 16, vg + j * 8);
            }
            if (tid < 4) cp16(cvta_s(&MskW[cur][tid * 4]), mp + s0n + tid * 16);
            CP_COMMIT();
        }
    }

    // ---- epilogue: normalize, emit hi/lo fp16 split at [B*T, D] ----
    {
        float inv0 = (l0 > 0.f) ? (1.0f / l0) : 0.f;
        float inv1 = (l1 > 0.f) ? (1.0f / l1) : 0.f;
        size_t r0 = ((size_t)(b * NT + t0 + w16 + g))     * ND + h * NHD;
        size_t r1 = ((size_t)(b * NT + t0 + w16 + g + 8)) * ND + h * NHD;
#pragma unroll
        for (int nb = 0; nb < 8; nb++) {
            int c = nb * 8 + 2 * q;
            float x0 = O[nb][0] * inv0, x1 = O[nb][1] * inv0;
            float x2 = O[nb][2] * inv1, x3 = O[nb][3] * inv1;
            __half h0 = __float2half_rn(x0), h1 = __float2half_rn(x1);
            __half h2 = __float2half_rn(x2), h3 = __float2half_rn(x3);
            *(__half2*)&outh[r0 + c] = __halves2half2(h0, h1);
            *(__half2*)&outh[r1 + c] = __halves2half2(h2, h3);
            *(__half2*)&outl[r0 + c] = __floats2half2_rn(
                x0 - __half2float(h0), x1 - __half2float(h1));
            *(__half2*)&outl[r1 + c] = __floats2half2_rn(
                x2 - __half2float(h2), x3 - __half2float(h3));
        }
    }
}

// ---------------------------------------------------------------------------
extern "C" void kernel_launch(void* const* d_in, const int* in_sizes, int n_in,
                              void* d_out, int out_size)
{
    const float* query = (const float*)d_in[0];
    const float* key   = (const float*)d_in[1];
    const float* value = (const float*)d_in[2];
    const unsigned char* mask = (const unsigned char*)d_in[3];
    const float* Wq = (const float*)d_in[4];
    const float* bq = (const float*)d_in[5];
    const float* Wk = (const float*)d_in[6];
    const float* bk = (const float*)d_in[7];
    const float* Wv = (const float*)d_in[8];
    const float* bv = (const float*)d_in[9];
    const float* Wo = (const float*)d_in[10];
    const float* bo = (const float*)d_in[11];
    float* out = (float*)d_out;

    __half *qb, *kb, *vb, *ah, *al, *wh, *wl, *oh, *ol;
    cudaGetSymbolAddress((void**)&qb, g_q);
    cudaGetSymbolAddress((void**)&kb, g_k);
    cudaGetSymbolAddress((void**)&vb, g_v);
    cudaGetSymbolAddress((void**)&ah, g_ah);
    cudaGetSymbolAddress((void**)&al, g_al);
    cudaGetSymbolAddress((void**)&wh, g_wh);
    cudaGetSymbolAddress((void**)&wl, g_wl);
    cudaGetSymbolAddress((void**)&oh, g_oh);
    cudaGetSymbolAddress((void**)&ol, g_ol);

    const int smem3 = G2_ST * 2 * (int)sizeof(__half);   // 61440 B
    cudaFuncSetAttribute(gemm3_kernel,
                         cudaFuncAttributeMaxDynamicSharedMemorySize, smem3);

    const int NW = ND * ND;               // 262144 per weight
    const int NA = NB * NT * ND;          // 8388608 per activation

    split_kernel<<<NW / 1024, 256>>>(Wq, wh + 0 * NW, wl + 0 * NW, NW);
    split_kernel<<<NW / 1024, 256>>>(Wk, wh + 1 * NW, wl + 1 * NW, NW);
    split_kernel<<<NW / 1024, 256>>>(Wv, wh + 2 * NW, wl + 2 * NW, NW);
    split_kernel<<<NW / 1024, 256>>>(Wo, wh + 3 * NW, wl + 3 * NW, NW);
    split_kernel<<<NA / 1024, 256>>>(query, ah + 0L * NA, al + 0L * NA, NA);
    split_kernel<<<NA / 1024, 256>>>(key,   ah + 1L * NA, al + 1L * NA, NA);
    split_kernel<<<NA / 1024, 256>>>(value, ah + 2L * NA, al + 2L * NA, NA);

    dim3 gg(ND / 64, (NB * NT) / 128);    // (8, 128)
    gemm3_kernel<<<gg, 128, smem3>>>(ah + 0L * NA, al + 0L * NA,
                                     wh + 0 * NW, wl + 0 * NW, bq, qb, 1);
    gemm3_kernel<<<gg, 128, smem3>>>(ah + 1L * NA, al + 1L * NA,
                                     wh + 1 * NW, wl + 1 * NW, bk, kb, 1);
    gemm3_kernel<<<gg, 128, smem3>>>(ah + 2L * NA, al + 2L * NA,
                                     wh + 2 * NW, wl + 2 * NW, bv, vb, 1);

    dim3 ga(NT / 64, NH, NB);             // (64, 8, 4)
    attn_kernel<<<ga, 128>>>(qb, kb, vb, mask, oh, ol);

    gemm3_kernel<<<gg, 128, smem3>>>(oh, ol, wh + 3 * NW, wl + 3 * NW,
                                     bo, out, 0);
}

// round 10
// speedup vs baseline: 1.2087x; 1.1267x over previous
#include <cuda_runtime.h>
#include <cuda_fp16.h>
#include <math.h>
#include <stdint.h>

#define NB 4
#define NT 4096
#define NS 4096
#define ND 512
#define NH 8
#define NHD 64

// Scratch (allocation-free rule: __device__ globals)
__device__ __half g_q[NB * NH * NT * NHD];
__device__ __half g_k[NB * NH * NS * NHD];
__device__ __half g_v[NB * NH * NS * NHD];
__device__ __half g_ah[3 * NB * NT * ND];   // hi split of query|key|value
__device__ __half g_al[3 * NB * NT * ND];   // lo split
__device__ __half g_wh[4 * ND * ND];        // hi split of Wq|Wk|Wv|Wo
__device__ __half g_wl[4 * ND * ND];
__device__ __half g_oh[NB * NT * ND];       // hi split of attention output
__device__ __half g_ol[NB * NT * ND];

// ===========================================================================
// helpers
// ===========================================================================
__device__ __forceinline__ float ex2f(float x) {
    float y;
    asm("ex2.approx.ftz.f32 %0, %1;" : "=f"(y) : "f"(x));
    return y;
}
__device__ __forceinline__ uint32_t packh2(float lo, float hi) {
    __half2 h = __floats2half2_rn(lo, hi);
    return *reinterpret_cast<uint32_t*>(&h);
}
__device__ __forceinline__ uint32_t cvta_s(const void* p) {
    return (uint32_t)__cvta_generic_to_shared(p);
}
// D += A * B  (m16n8k16 fp16 in, fp32 accum; A row-major, B col-major)
__device__ __forceinline__ void mma_f16(float* d, const uint32_t* a,
                                        uint32_t b0, uint32_t b1) {
    asm volatile(
        "mma.sync.aligned.m16n8k16.row.col.f32.f16.f16.f32 "
        "{%0,%1,%2,%3}, {%4,%5,%6,%7}, {%8,%9}, {%0,%1,%2,%3};"
        : "+f"(d[0]), "+f"(d[1]), "+f"(d[2]), "+f"(d[3])
        : "r"(a[0]), "r"(a[1]), "r"(a[2]), "r"(a[3]), "r"(b0), "r"(b1));
}
__device__ __forceinline__ void ldsm4(uint32_t* r, uint32_t addr) {
    asm volatile("ldmatrix.sync.aligned.m8n8.x4.shared.b16 {%0,%1,%2,%3}, [%4];"
                 : "=r"(r[0]), "=r"(r[1]), "=r"(r[2]), "=r"(r[3]) : "r"(addr));
}
__device__ __forceinline__ void ldsm4t(uint32_t* r, uint32_t addr) {
    asm volatile("ldmatrix.sync.aligned.m8n8.x4.trans.shared.b16 {%0,%1,%2,%3}, [%4];"
                 : "=r"(r[0]), "=r"(r[1]), "=r"(r[2]), "=r"(r[3]) : "r"(addr));
}
__device__ __forceinline__ void cp16(uint32_t dst, const void* src) {
    asm volatile("cp.async.cg.shared.global [%0], [%1], 16;" :: "r"(dst), "l"(src));
}
#define CP_COMMIT() asm volatile("cp.async.commit_group;")
#define CP_WAIT1()  asm volatile("cp.async.wait_group 1;")
#define CP_WAIT0()  asm volatile("cp.async.wait_group 0;")

// ---------------------------------------------------------------------------
// split: fp32 -> (hi fp16, lo fp16) with v = hi + lo + O(2^-22)
// ---------------------------------------------------------------------------
__global__ __launch_bounds__(256)
void split_kernel(const float* __restrict__ in, __half* __restrict__ hi,
                  __half* __restrict__ lo, int n)
{
    int i = (blockIdx.x * 256 + threadIdx.x) * 4;
    if (i >= n) return;
    float4 v = *(const float4*)(in + i);
    __half h[4], l[4];
    h[0] = __float2half_rn(v.x); l[0] = __float2half_rn(v.x - __half2float(h[0]));
    h[1] = __float2half_rn(v.y); l[1] = __float2half_rn(v.y - __half2float(h[1]));
    h[2] = __float2half_rn(v.z); l[2] = __float2half_rn(v.z - __half2float(h[2]));
    h[3] = __float2half_rn(v.w); l[3] = __float2half_rn(v.w - __half2float(h[3]));
    *(uint2*)(hi + i) = *(uint2*)h;
    *(uint2*)(lo + i) = *(uint2*)l;
}

// ---------------------------------------------------------------------------
// 3-term split-fp16 GEMM v3: out = (Ah+Al) @ (Wh+Wl)^T + b, keeping
// Ah*Wh + Ah*Wl + Al*Wh (error ~2^-22).
// CTA: 256 thr / 8 warps; M=128 (16 rows/warp, NO rf-doubling) x N=64;
// K-step 32; cp.async double-buffered 61.4 KB -> 3 CTAs/SM (24 warps).
// head_layout=1: fp16 out to [B,H,T,64] (N-tile == head); else fp32 [M,512].
// ---------------------------------------------------------------------------
#define G2_AH 0                       // offsets in halves within a stage
#define G2_AL (128 * 40)
#define G2_WH (2 * 128 * 40)
#define G2_WL (2 * 128 * 40 + 64 * 40)
#define G2_ST (2 * 128 * 40 + 2 * 64 * 40)   // 15360 halves per stage

__global__ __launch_bounds__(256, 3)
void gemm3_kernel(const __half* __restrict__ Ah, const __half* __restrict__ Al,
                  const __half* __restrict__ Wh, const __half* __restrict__ Wl,
                  const float* __restrict__ bias, void* __restrict__ outp,
                  int head_layout)
{
    extern __shared__ __half dsm[];

    const int tid  = threadIdx.x;
    const int warp = tid >> 5, lane = tid & 31;
    const int g = lane >> 2, q = lane & 3;
    const int m0 = blockIdx.y * 128;
    const int n0 = blockIdx.x * 64;

    // loaders: A 128x32 (2 thr/row, 2 cp16 each for hi and lo),
    //          W 64x32  (4 thr/row, 1 cp16 each for hi and lo)
    const int arow = tid >> 1, acb = (tid & 1) * 16;
    const int wrow = tid >> 2, wcb = (tid & 3) * 8;

    const __half* Agh = Ah + (size_t)(m0 + arow) * ND + acb;
    const __half* Agl = Al + (size_t)(m0 + arow) * ND + acb;
    const __half* Wgh = Wh + (size_t)(n0 + wrow) * ND + wcb;
    const __half* Wgl = Wl + (size_t)(n0 + wrow) * ND + wcb;

    float D[8][4];
#pragma unroll
    for (int nb = 0; nb < 8; nb++)
#pragma unroll
        for (int i = 0; i < 4; i++) D[nb][i] = 0.f;

    auto load_stage = [&](int stage, int k0) {
        __half* base = dsm + (stage & 1) * G2_ST;
        uint32_t ah = cvta_s(base + G2_AH + arow * 40 + acb);
        uint32_t al = cvta_s(base + G2_AL + arow * 40 + acb);
        uint32_t wh = cvta_s(base + G2_WH + wrow * 40 + wcb);
        uint32_t wl = cvta_s(base + G2_WL + wrow * 40 + wcb);
#pragma unroll
        for (int j = 0; j < 2; j++) {
            cp16(ah + j * 16, Agh + k0 + j * 8);
            cp16(al + j * 16, Agl + k0 + j * 8);
        }
        cp16(wh, Wgh + k0);
        cp16(wl, Wgl + k0);
        CP_COMMIT();
    };

    load_stage(0, 0);
    load_stage(1, 32);

#pragma unroll 1
    for (int it = 0; it < ND / 32; it++) {
        const __half* base = dsm + (it & 1) * G2_ST;

        if (it < ND / 32 - 1) { CP_WAIT1(); } else { CP_WAIT0(); }
        __syncthreads();

#pragma unroll
        for (int kc = 0; kc < 2; kc++) {
            int arw = warp * 16 + (lane & 15);
            int acl = kc * 16 + (lane >> 4) * 8;
            uint32_t ahf[4], alf[4];
            ldsm4(ahf, cvta_s(base + G2_AH + arw * 40 + acl));
            ldsm4(alf, cvta_s(base + G2_AL + arw * 40 + acl));
#pragma unroll
            for (int nbp = 0; nbp < 4; nbp++) {
                int row = nbp * 16 + ((lane >> 4) & 1) * 8 + (lane & 7);
                int col = kc * 16 + ((lane >> 3) & 1) * 8;
                uint32_t bh[4], bl[4];
                ldsm4(bh, cvta_s(base + G2_WH + row * 40 + col));
                ldsm4(bl, cvta_s(base + G2_WL + row * 40 + col));
                mma_f16(D[2 * nbp],     ahf, bh[0], bh[1]);
                mma_f16(D[2 * nbp + 1], ahf, bh[2], bh[3]);
                mma_f16(D[2 * nbp],     alf, bh[0], bh[1]);
                mma_f16(D[2 * nbp + 1], alf, bh[2], bh[3]);
                mma_f16(D[2 * nbp],     ahf, bl[0], bl[1]);
                mma_f16(D[2 * nbp + 1], ahf, bl[2], bl[3]);
            }
        }
        __syncthreads();
        if (it + 2 < ND / 32) load_stage(it + 2, (it + 2) * 32);
    }

    // ---- epilogue ----
    const float* bp = bias + n0;
    const int mg = m0 + warp * 16 + g;
#pragma unroll
    for (int nb = 0; nb < 8; nb++) {
        int c = nb * 8 + 2 * q;
        float2 bb = *(const float2*)(bp + c);
        float o00 = D[nb][0] + bb.x, o01 = D[nb][1] + bb.y;   // row mg
        float o10 = D[nb][2] + bb.x, o11 = D[nb][3] + bb.y;   // row mg+8
        if (head_layout) {
            int h = n0 >> 6;
            int bbi = mg >> 12, t = mg & 4095;
            __half* oh = (__half*)outp;
            size_t bse = ((size_t)(bbi * NH + h) * NT + t) * NHD + c;
            *(__half2*)&oh[bse]           = __floats2half2_rn(o00, o01);
            *(__half2*)&oh[bse + 8 * NHD] = __floats2half2_rn(o10, o11);
        } else {
            float* of = (float*)outp;
            size_t bse = (size_t)mg * ND + n0 + c;
            *(float2*)&of[bse]          = make_float2(o00, o01);
            *(float2*)&of[bse + 8 * ND] = make_float2(o10, o11);
        }
    }
}

// ---------------------------------------------------------------------------
// fp16 flash attention v4 (R7, proven 609us): 4 warps/CTA, 16 rows/warp,
// cp.async double-buffered K/V, ldmatrix frags, P in regs, row sums via
// P@ones MMA, skip-rescale, mask fast path. Emits hi/lo fp16 output split.
// ---------------------------------------------------------------------------
__global__ __launch_bounds__(128)
void attn_kernel(const __half* __restrict__ Qh, const __half* __restrict__ Kh,
                 const __half* __restrict__ Vh,
                 const unsigned char* __restrict__ mask,
                 __half* __restrict__ outh, __half* __restrict__ outl)
{
    __shared__ __half Ksh[2][64][72];   // K tile [s][d], double-buffered
    __shared__ __half Vsh[2][64][72];   // V tile [s][d], double-buffered
    __shared__ uint32_t MskW[2][16];    // 64 mask bytes / buffer

    const int b  = blockIdx.z;
    const int h  = blockIdx.y;
    const int t0 = blockIdx.x * 64;
    const int tid  = threadIdx.x;
    const int warp = tid >> 5;
    const int lane = tid & 31;
    const int g = lane >> 2;
    const int q = lane & 3;
    const int w16 = warp * 16;
    const uint32_t ONES = 0x3C003C00u;   // half2(1,1)

    const __half* Kp = Kh + (size_t)(b * NH + h) * NS * NHD;
    const __half* Vp = Vh + (size_t)(b * NH + h) * NS * NHD;
    const unsigned char* mp = mask + (size_t)b * NS;

    const int lrow = tid >> 1;
    const int lcol = (tid & 1) * 32;

    // ---- Q fragments (fp16 regs, once), scale 0.125*log2(e) ----
    uint32_t Qf[4][4];
    {
        const __half2 qs2 = __float2half2_rn(0.125f * 1.4426950408889634f);
        const __half* Q0 = Qh + ((size_t)(b * NH + h) * NT + t0 + w16 + g) * NHD;
        const __half* Q1 = Q0 + 8 * NHD;
#pragma unroll
        for (int kc = 0; kc < 4; kc++) {
            __half2 x0 = __hmul2(*(const __half2*)(Q0 + kc * 16 + 2 * q),     qs2);
            __half2 x1 = __hmul2(*(const __half2*)(Q1 + kc * 16 + 2 * q),     qs2);
            __half2 x2 = __hmul2(*(const __half2*)(Q0 + kc * 16 + 2 * q + 8), qs2);
            __half2 x3 = __hmul2(*(const __half2*)(Q1 + kc * 16 + 2 * q + 8), qs2);
            Qf[kc][0] = *(uint32_t*)&x0;
            Qf[kc][1] = *(uint32_t*)&x1;
            Qf[kc][2] = *(uint32_t*)&x2;
            Qf[kc][3] = *(uint32_t*)&x3;
        }
    }

    float O[8][4];
#pragma unroll
    for (int nb = 0; nb < 8; nb++)
#pragma unroll
        for (int i = 0; i < 4; i++) O[nb][i] = 0.f;
    float m0 = -INFINITY, m1 = -INFINITY, l0 = 0.f, l1 = 0.f;

    // ---- prologue: async-load tiles 0 and 1 ----
#pragma unroll
    for (int t = 0; t < 2; t++) {
        const __half* kg = Kp + (size_t)(t * 64 + lrow) * NHD + lcol;
        const __half* vg = Vp + (size_t)(t * 64 + lrow) * NHD + lcol;
        uint32_t kd = cvta_s(&Ksh[t][lrow][lcol]);
        uint32_t vd = cvta_s(&Vsh[t][lrow][lcol]);
#pragma unroll
        for (int j = 0; j < 4; j++) {
            cp16(kd + j * 16, kg + j * 8);
            cp16(vd + j * 16, vg + j * 8);
        }
        if (tid < 4) cp16(cvta_s(&MskW[t][tid * 4]), mp + t * 64 + tid * 16);
        CP_COMMIT();
    }

#pragma unroll 1
    for (int it = 0; it < NS / 64; it++) {
        const int cur = it & 1;
        if (it < NS / 64 - 1) { CP_WAIT1(); } else { CP_WAIT0(); }
        int any = __syncthreads_or((tid < 16) ? (int)(MskW[cur][tid] != 0u) : 0);

        // ---- QK^T via ldmatrix(non-trans) B-frags ----
        float D[8][4];
#pragma unroll
        for (int nb = 0; nb < 8; nb++) {
            D[nb][0] = 0.f; D[nb][1] = 0.f; D[nb][2] = 0.f; D[nb][3] = 0.f;
        }
#pragma unroll
        for (int kc = 0; kc < 4; kc++) {
#pragma unroll
            for (int nbp = 0; nbp < 4; nbp++) {
                int row = nbp * 16 + ((lane >> 4) & 1) * 8 + (lane & 7);
                int col = kc * 16 + ((lane >> 3) & 1) * 8;
                uint32_t bf[4];
                ldsm4(bf, cvta_s(&Ksh[cur][row][col]));
                mma_f16(D[2 * nbp],     Qf[kc], bf[0], bf[1]);
                mma_f16(D[2 * nbp + 1], Qf[kc], bf[2], bf[3]);
            }
        }

        // ---- mask (fast path skips when tile unmasked) ----
        if (any) {
            const unsigned char* Msk = (const unsigned char*)&MskW[cur][0];
#pragma unroll
            for (int nb = 0; nb < 8; nb++) {
                int c0 = nb * 8 + 2 * q;
                if (Msk[c0])     { D[nb][0] = -INFINITY; D[nb][2] = -INFINITY; }
                if (Msk[c0 + 1]) { D[nb][1] = -INFINITY; D[nb][3] = -INFINITY; }
            }
        }

        // ---- online softmax (log2 domain); rows g, g+8 ----
        float ml0 = -INFINITY, ml1 = -INFINITY;
#pragma unroll
        for (int nb = 0; nb < 8; nb++) {
            ml0 = fmaxf(ml0, fmaxf(D[nb][0], D[nb][1]));
            ml1 = fmaxf(ml1, fmaxf(D[nb][2], D[nb][3]));
        }
        ml0 = fmaxf(ml0, __shfl_xor_sync(0xffffffffu, ml0, 1));
        ml0 = fmaxf(ml0, __shfl_xor_sync(0xffffffffu, ml0, 2));
        ml1 = fmaxf(ml1, __shfl_xor_sync(0xffffffffu, ml1, 1));
        ml1 = fmaxf(ml1, __shfl_xor_sync(0xffffffffu, ml1, 2));

        float mn0 = fmaxf(m0, ml0), mn1 = fmaxf(m1, ml1);
        float ms0 = (mn0 == -INFINITY) ? 0.f : mn0;
        float ms1 = (mn1 == -INFINITY) ? 0.f : mn1;
#pragma unroll
        for (int nb = 0; nb < 8; nb++) {
            D[nb][0] = ex2f(D[nb][0] - ms0);
            D[nb][1] = ex2f(D[nb][1] - ms0);
            D[nb][2] = ex2f(D[nb][2] - ms1);
            D[nb][3] = ex2f(D[nb][3] - ms1);
        }

        float f0 = ex2f(m0 - ms0);   // exact 1.0 when max unchanged
        float f1 = ex2f(m1 - ms1);
        if (ml0 > m0 || ml1 > m1) {  // rescale only when a max moved
#pragma unroll
            for (int nb = 0; nb < 8; nb++) {
                O[nb][0] *= f0; O[nb][1] *= f0;
                O[nb][2] *= f1; O[nb][3] *= f1;
            }
        }
        m0 = mn0; m1 = mn1;

        // ---- O += P @ V ; row sums via P @ ones ----
        float Ssum[4] = {0.f, 0.f, 0.f, 0.f};
#pragma unroll
        for (int kk = 0; kk < 4; kk++) {
            uint32_t a[4];
            a[0] = packh2(D[2 * kk][0],     D[2 * kk][1]);
            a[1] = packh2(D[2 * kk][2],     D[2 * kk][3]);
            a[2] = packh2(D[2 * kk + 1][0], D[2 * kk + 1][1]);
            a[3] = packh2(D[2 * kk + 1][2], D[2 * kk + 1][3]);
            mma_f16(Ssum, a, ONES, ONES);
#pragma unroll
            for (int nbp = 0; nbp < 4; nbp++) {
                int row = kk * 16 + ((lane >> 3) & 1) * 8 + (lane & 7);
                int col = nbp * 16 + ((lane >> 4) & 1) * 8;
                uint32_t bf[4];
                ldsm4t(bf, cvta_s(&Vsh[cur][row][col]));
                mma_f16(O[2 * nbp],     a, bf[0], bf[1]);
                mma_f16(O[2 * nbp + 1], a, bf[2], bf[3]);
            }
        }
        l0 = l0 * f0 + Ssum[0];
        l1 = l1 * f1 + Ssum[2];

        __syncthreads();   // all reads of buf `cur` done
        if (it + 2 < NS / 64) {
            int s0n = (it + 2) * 64;
            const __half* kg = Kp + (size_t)(s0n + lrow) * NHD + lcol;
            const __half* vg = Vp + (size_t)(s0n + lrow) * NHD + lcol;
            uint32_t kd = cvta_s(&Ksh[cur][lrow][lcol]);
            uint32_t vd = cvta_s(&Vsh[cur][lrow][lcol]);
#pragma unroll
            for (int j = 0; j < 4; j++) {
                cp16(kd + j * 16, kg + j * 8);
                cp16(vd + j * 16, vg + j * 8);
            }
            if (tid < 4) cp16(cvta_s(&MskW[cur][tid * 4]), mp + s0n + tid * 16);
            CP_COMMIT();
        }
    }

    // ---- epilogue: normalize, emit hi/lo fp16 split at [B*T, D] ----
    {
        float inv0 = (l0 > 0.f) ? (1.0f / l0) : 0.f;
        float inv1 = (l1 > 0.f) ? (1.0f / l1) : 0.f;
        size_t r0 = ((size_t)(b * NT + t0 + w16 + g))     * ND + h * NHD;
        size_t r1 = ((size_t)(b * NT + t0 + w16 + g + 8)) * ND + h * NHD;
#pragma unroll
        for (int nb = 0; nb < 8; nb++) {
            int c = nb * 8 + 2 * q;
            float x0 = O[nb][0] * inv0, x1 = O[nb][1] * inv0;
            float x2 = O[nb][2] * inv1, x3 = O[nb][3] * inv1;
            __half h0 = __float2half_rn(x0), h1 = __float2half_rn(x1);
            __half h2 = __float2half_rn(x2), h3 = __float2half_rn(x3);
            *(__half2*)&outh[r0 + c] = __halves2half2(h0, h1);
            *(__half2*)&outh[r1 + c] = __halves2half2(h2, h3);
            *(__half2*)&outl[r0 + c] = __floats2half2_rn(
                x0 - __half2float(h0), x1 - __half2float(h1));
            *(__half2*)&outl[r1 + c] = __floats2half2_rn(
                x2 - __half2float(h2), x3 - __half2float(h3));
        }
    }
}

// ---------------------------------------------------------------------------
extern "C" void kernel_launch(void* const* d_in, const int* in_sizes, int n_in,
                              void* d_out, int out_size)
{
    const float* query = (const float*)d_in[0];
    const float* key   = (const float*)d_in[1];
    const float* value = (const float*)d_in[2];
    const unsigned char* mask = (const unsigned char*)d_in[3];
    const float* Wq = (const float*)d_in[4];
    const float* bq = (const float*)d_in[5];
    const float* Wk = (const float*)d_in[6];
    const float* bk = (const float*)d_in[7];
    const float* Wv = (const float*)d_in[8];
    const float* bv = (const float*)d_in[9];
    const float* Wo = (const float*)d_in[10];
    const float* bo = (const float*)d_in[11];
    float* out = (float*)d_out;

    __half *qb, *kb, *vb, *ah, *al, *wh, *wl, *oh, *ol;
    cudaGetSymbolAddress((void**)&qb, g_q);
    cudaGetSymbolAddress((void**)&kb, g_k);
    cudaGetSymbolAddress((void**)&vb, g_v);
    cudaGetSymbolAddress((void**)&ah, g_ah);
    cudaGetSymbolAddress((void**)&al, g_al);
    cudaGetSymbolAddress((void**)&wh, g_wh);
    cudaGetSymbolAddress((void**)&wl, g_wl);
    cudaGetSymbolAddress((void**)&oh, g_oh);
    cudaGetSymbolAddress((void**)&ol, g_ol);

    const int smem3 = G2_ST * 2 * (int)sizeof(__half);   // 61440 B
    cudaFuncSetAttribute(gemm3_kernel,
                         cudaFuncAttributeMaxDynamicSharedMemorySize, smem3);

    const int NW = ND * ND;               // 262144 per weight
    const int NA = NB * NT * ND;          // 8388608 per activation

    split_kernel<<<NW / 1024, 256>>>(Wq, wh + 0 * NW, wl + 0 * NW, NW);
    split_kernel<<<NW / 1024, 256>>>(Wk, wh + 1 * NW, wl + 1 * NW, NW);
    split_kernel<<<NW / 1024, 256>>>(Wv, wh + 2 * NW, wl + 2 * NW, NW);
    split_kernel<<<NW / 1024, 256>>>(Wo, wh + 3 * NW, wl + 3 * NW, NW);
    split_kernel<<<NA / 1024, 256>>>(query, ah + 0L * NA, al + 0L * NA, NA);
    split_kernel<<<NA / 1024, 256>>>(key,   ah + 1L * NA, al + 1L * NA, NA);
    split_kernel<<<NA / 1024, 256>>>(value, ah + 2L * NA, al + 2L * NA, NA);

    dim3 gg(ND / 64, (NB * NT) / 128);    // (8, 128)
    gemm3_kernel<<<gg, 256, smem3>>>(ah + 0L * NA, al + 0L * NA,
                                     wh + 0 * NW, wl + 0 * NW, bq, qb, 1);
    gemm3_kernel<<<gg, 256, smem3>>>(ah + 1L * NA, al + 1L * NA,
                                     wh + 1 * NW, wl + 1 * NW, bk, kb, 1);
    gemm3_kernel<<<gg, 256, smem3>>>(ah + 2L * NA, al + 2L * NA,
                                     wh + 2 * NW, wl + 2 * NW, bv, vb, 1);

    dim3 ga(NT / 64, NH, NB);             // (64, 8, 4)
    attn_kernel<<<ga, 128>>>(qb, kb, vb, mask, oh, ol);

    gemm3_kernel<<<gg, 256, smem3>>>(oh, ol, wh + 3 * NW, wl + 3 * NW,
                                     bo, out, 0);
}

// round 11
// speedup vs baseline: 1.2660x; 1.0474x over previous
#include <cuda_runtime.h>
#include <cuda_fp16.h>
#include <math.h>
#include <stdint.h>

#define NB 4
#define NT 4096
#define NS 4096
#define ND 512
#define NH 8
#define NHD 64

// Scratch (allocation-free rule: __device__ globals)
__device__ __half g_q[NB * NH * NT * NHD];
__device__ __half g_k[NB * NH * NS * NHD];
__device__ __half g_v[NB * NH * NS * NHD];
__device__ __half g_ah[3 * NB * NT * ND];   // hi split of query|key|value
__device__ __half g_al[3 * NB * NT * ND];   // lo split
__device__ __half g_wh[4 * ND * ND];        // hi split of Wq|Wk|Wv|Wo
__device__ __half g_wl[4 * ND * ND];
__device__ __half g_oh[NB * NT * ND];       // hi split of attention output
__device__ __half g_ol[NB * NT * ND];

// ===========================================================================
// helpers
// ===========================================================================
__device__ __forceinline__ float ex2f(float x) {
    float y;
    asm("ex2.approx.ftz.f32 %0, %1;" : "=f"(y) : "f"(x));
    return y;
}
__device__ __forceinline__ uint32_t packh2(float lo, float hi) {
    __half2 h = __floats2half2_rn(lo, hi);
    return *reinterpret_cast<uint32_t*>(&h);
}
__device__ __forceinline__ uint32_t cvta_s(const void* p) {
    return (uint32_t)__cvta_generic_to_shared(p);
}
// D += A * B  (m16n8k16 fp16 in, fp32 accum; A row-major, B col-major)
__device__ __forceinline__ void mma_f16(float* d, const uint32_t* a,
                                        uint32_t b0, uint32_t b1) {
    asm volatile(
        "mma.sync.aligned.m16n8k16.row.col.f32.f16.f16.f32 "
        "{%0,%1,%2,%3}, {%4,%5,%6,%7}, {%8,%9}, {%0,%1,%2,%3};"
        : "+f"(d[0]), "+f"(d[1]), "+f"(d[2]), "+f"(d[3])
        : "r"(a[0]), "r"(a[1]), "r"(a[2]), "r"(a[3]), "r"(b0), "r"(b1));
}
__device__ __forceinline__ void ldsm4(uint32_t* r, uint32_t addr) {
    asm volatile("ldmatrix.sync.aligned.m8n8.x4.shared.b16 {%0,%1,%2,%3}, [%4];"
                 : "=r"(r[0]), "=r"(r[1]), "=r"(r[2]), "=r"(r[3]) : "r"(addr));
}
__device__ __forceinline__ void ldsm4t(uint32_t* r, uint32_t addr) {
    asm volatile("ldmatrix.sync.aligned.m8n8.x4.trans.shared.b16 {%0,%1,%2,%3}, [%4];"
                 : "=r"(r[0]), "=r"(r[1]), "=r"(r[2]), "=r"(r[3]) : "r"(addr));
}
__device__ __forceinline__ void cp16(uint32_t dst, const void* src) {
    asm volatile("cp.async.cg.shared.global [%0], [%1], 16;" :: "r"(dst), "l"(src));
}
#define CP_COMMIT() asm volatile("cp.async.commit_group;")
#define CP_WAIT1()  asm volatile("cp.async.wait_group 1;")
#define CP_WAIT0()  asm volatile("cp.async.wait_group 0;")

// ---------------------------------------------------------------------------
// fused split: fp32 -> (hi, lo) fp16; blockIdx.y selects one of <=4 tensors
// ---------------------------------------------------------------------------
__global__ __launch_bounds__(256)
void split4_kernel(const float* __restrict__ i0, const float* __restrict__ i1,
                   const float* __restrict__ i2, const float* __restrict__ i3,
                   __half* __restrict__ hi, __half* __restrict__ lo, int n)
{
    const float* in = (blockIdx.y == 0) ? i0 : (blockIdx.y == 1) ? i1
                    : (blockIdx.y == 2) ? i2 : i3;
    const size_t off = (size_t)blockIdx.y * n;
    int i = (blockIdx.x * 256 + threadIdx.x) * 4;
    if (i >= n) return;
    float4 v = *(const float4*)(in + i);
    __half h[4], l[4];
    h[0] = __float2half_rn(v.x); l[0] = __float2half_rn(v.x - __half2float(h[0]));
    h[1] = __float2half_rn(v.y); l[1] = __float2half_rn(v.y - __half2float(h[1]));
    h[2] = __float2half_rn(v.z); l[2] = __float2half_rn(v.z - __half2float(h[2]));
    h[3] = __float2half_rn(v.w); l[3] = __float2half_rn(v.w - __half2float(h[3]));
    *(uint2*)(hi + off + i) = *(uint2*)h;
    *(uint2*)(lo + off + i) = *(uint2*)l;
}

// ---------------------------------------------------------------------------
// 3-term split-fp16 GEMM v3 (R10, proven): out = (Ah+Al) @ (Wh+Wl)^T + b,
// keeping Ah*Wh + Ah*Wl + Al*Wh. 256 thr / 8 warps; M=128 x N=64; K-step 32;
// cp.async double-buffered 61.4 KB -> 3 CTAs/SM.
// ---------------------------------------------------------------------------
#define G2_AH 0                       // offsets in halves within a stage
#define G2_AL (128 * 40)
#define G2_WH (2 * 128 * 40)
#define G2_WL (2 * 128 * 40 + 64 * 40)
#define G2_ST (2 * 128 * 40 + 2 * 64 * 40)   // 15360 halves per stage

__global__ __launch_bounds__(256, 3)
void gemm3_kernel(const __half* __restrict__ Ah, const __half* __restrict__ Al,
                  const __half* __restrict__ Wh, const __half* __restrict__ Wl,
                  const float* __restrict__ bias, void* __restrict__ outp,
                  int head_layout)
{
    extern __shared__ __half dsm[];

    const int tid  = threadIdx.x;
    const int warp = tid >> 5, lane = tid & 31;
    const int g = lane >> 2, q = lane & 3;
    const int m0 = blockIdx.y * 128;
    const int n0 = blockIdx.x * 64;

    const int arow = tid >> 1, acb = (tid & 1) * 16;
    const int wrow = tid >> 2, wcb = (tid & 3) * 8;

    const __half* Agh = Ah + (size_t)(m0 + arow) * ND + acb;
    const __half* Agl = Al + (size_t)(m0 + arow) * ND + acb;
    const __half* Wgh = Wh + (size_t)(n0 + wrow) * ND + wcb;
    const __half* Wgl = Wl + (size_t)(n0 + wrow) * ND + wcb;

    float D[8][4];
#pragma unroll
    for (int nb = 0; nb < 8; nb++)
#pragma unroll
        for (int i = 0; i < 4; i++) D[nb][i] = 0.f;

    auto load_stage = [&](int stage, int k0) {
        __half* base = dsm + (stage & 1) * G2_ST;
        uint32_t ah = cvta_s(base + G2_AH + arow * 40 + acb);
        uint32_t al = cvta_s(base + G2_AL + arow * 40 + acb);
        uint32_t wh = cvta_s(base + G2_WH + wrow * 40 + wcb);
        uint32_t wl = cvta_s(base + G2_WL + wrow * 40 + wcb);
#pragma unroll
        for (int j = 0; j < 2; j++) {
            cp16(ah + j * 16, Agh + k0 + j * 8);
            cp16(al + j * 16, Agl + k0 + j * 8);
        }
        cp16(wh, Wgh + k0);
        cp16(wl, Wgl + k0);
        CP_COMMIT();
    };

    load_stage(0, 0);
    load_stage(1, 32);

#pragma unroll 1
    for (int it = 0; it < ND / 32; it++) {
        const __half* base = dsm + (it & 1) * G2_ST;

        if (it < ND / 32 - 1) { CP_WAIT1(); } else { CP_WAIT0(); }
        __syncthreads();

#pragma unroll
        for (int kc = 0; kc < 2; kc++) {
            int arw = warp * 16 + (lane & 15);
            int acl = kc * 16 + (lane >> 4) * 8;
            uint32_t ahf[4], alf[4];
            ldsm4(ahf, cvta_s(base + G2_AH + arw * 40 + acl));
            ldsm4(alf, cvta_s(base + G2_AL + arw * 40 + acl));
#pragma unroll
            for (int nbp = 0; nbp < 4; nbp++) {
                int row = nbp * 16 + ((lane >> 4) & 1) * 8 + (lane & 7);
                int col = kc * 16 + ((lane >> 3) & 1) * 8;
                uint32_t bh[4], bl[4];
                ldsm4(bh, cvta_s(base + G2_WH + row * 40 + col));
                ldsm4(bl, cvta_s(base + G2_WL + row * 40 + col));
                mma_f16(D[2 * nbp],     ahf, bh[0], bh[1]);
                mma_f16(D[2 * nbp + 1], ahf, bh[2], bh[3]);
                mma_f16(D[2 * nbp],     alf, bh[0], bh[1]);
                mma_f16(D[2 * nbp + 1], alf, bh[2], bh[3]);
                mma_f16(D[2 * nbp],     ahf, bl[0], bl[1]);
                mma_f16(D[2 * nbp + 1], ahf, bl[2], bl[3]);
            }
        }
        __syncthreads();
        if (it + 2 < ND / 32) load_stage(it + 2, (it + 2) * 32);
    }

    // ---- epilogue ----
    const float* bp = bias + n0;
    const int mg = m0 + warp * 16 + g;
#pragma unroll
    for (int nb = 0; nb < 8; nb++) {
        int c = nb * 8 + 2 * q;
        float2 bb = *(const float2*)(bp + c);
        float o00 = D[nb][0] + bb.x, o01 = D[nb][1] + bb.y;   // row mg
        float o10 = D[nb][2] + bb.x, o11 = D[nb][3] + bb.y;   // row mg+8
        if (head_layout) {
            int h = n0 >> 6;
            int bbi = mg >> 12, t = mg & 4095;
            __half* oh = (__half*)outp;
            size_t bse = ((size_t)(bbi * NH + h) * NT + t) * NHD + c;
            *(__half2*)&oh[bse]           = __floats2half2_rn(o00, o01);
            *(__half2*)&oh[bse + 8 * NHD] = __floats2half2_rn(o10, o11);
        } else {
            float* of = (float*)outp;
            size_t bse = (size_t)mg * ND + n0 + c;
            *(float2*)&of[bse]          = make_float2(o00, o01);
            *(float2*)&of[bse + 8 * ND] = make_float2(o10, o11);
        }
    }
}

// ---------------------------------------------------------------------------
// fp16 flash attention v6: 3-stage ring-buffered K/V (dynamic smem 55.5 KB),
// ONE barrier per tile (tile it+2 lands in buf (it-1)%3, whose readers all
// passed this iteration's barrier). Otherwise identical math to v4:
// ldmatrix frags, P in regs, P@ones row sums, skip-rescale, mask fast path.
// ---------------------------------------------------------------------------
#define AT_TILE (64 * 72)                       // halves per K or V buffer
#define AT_MSK  (6 * AT_TILE)                   // mask offset (halves)
#define AT_SMEM (6 * AT_TILE * 2 + 3 * 64)      // bytes: 55296 + 192

__global__ __launch_bounds__(128)
void attn_kernel(const __half* __restrict__ Qh, const __half* __restrict__ Kh,
                 const __half* __restrict__ Vh,
                 const unsigned char* __restrict__ mask,
                 __half* __restrict__ outh, __half* __restrict__ outl)
{
    extern __shared__ __half asmem[];
    __half* Ksm = asmem;                 // [3][64][72]
    __half* Vsm = asmem + 3 * AT_TILE;   // [3][64][72]
    uint32_t* Mw = (uint32_t*)(asmem + AT_MSK);   // [3][16]

    const int b  = blockIdx.z;
    const int h  = blockIdx.y;
    const int t0 = blockIdx.x * 64;
    const int tid  = threadIdx.x;
    const int warp = tid >> 5;
    const int lane = tid & 31;
    const int g = lane >> 2;
    const int q = lane & 3;
    const int w16 = warp * 16;
    const uint32_t ONES = 0x3C003C00u;   // half2(1,1)

    const __half* Kp = Kh + (size_t)(b * NH + h) * NS * NHD;
    const __half* Vp = Vh + (size_t)(b * NH + h) * NS * NHD;
    const unsigned char* mp = mask + (size_t)b * NS;

    const int lrow = tid >> 1;
    const int lcol = (tid & 1) * 32;

    auto load_tile = [&](int t) {
        int buf = t % 3;
        const __half* kg = Kp + (size_t)(t * 64 + lrow) * NHD + lcol;
        const __half* vg = Vp + (size_t)(t * 64 + lrow) * NHD + lcol;
        uint32_t kd = cvta_s(Ksm + buf * AT_TILE + lrow * 72 + lcol);
        uint32_t vd = cvta_s(Vsm + buf * AT_TILE + lrow * 72 + lcol);
#pragma unroll
        for (int j = 0; j < 4; j++) {
            cp16(kd + j * 16, kg + j * 8);
            cp16(vd + j * 16, vg + j * 8);
        }
        if (tid < 4) cp16(cvta_s(Mw + buf * 16 + tid * 4), mp + t * 64 + tid * 16);
        CP_COMMIT();
    };

    // ---- Q fragments (fp16 regs, once), scale 0.125*log2(e) ----
    uint32_t Qf[4][4];
    {
        const __half2 qs2 = __float2half2_rn(0.125f * 1.4426950408889634f);
        const __half* Q0 = Qh + ((size_t)(b * NH + h) * NT + t0 + w16 + g) * NHD;
        const __half* Q1 = Q0 + 8 * NHD;
#pragma unroll
        for (int kc = 0; kc < 4; kc++) {
            __half2 x0 = __hmul2(*(const __half2*)(Q0 + kc * 16 + 2 * q),     qs2);
            __half2 x1 = __hmul2(*(const __half2*)(Q1 + kc * 16 + 2 * q),     qs2);
            __half2 x2 = __hmul2(*(const __half2*)(Q0 + kc * 16 + 2 * q + 8), qs2);
            __half2 x3 = __hmul2(*(const __half2*)(Q1 + kc * 16 + 2 * q + 8), qs2);
            Qf[kc][0] = *(uint32_t*)&x0;
            Qf[kc][1] = *(uint32_t*)&x1;
            Qf[kc][2] = *(uint32_t*)&x2;
            Qf[kc][3] = *(uint32_t*)&x3;
        }
    }

    float O[8][4];
#pragma unroll
    for (int nb = 0; nb < 8; nb++)
#pragma unroll
        for (int i = 0; i < 4; i++) O[nb][i] = 0.f;
    float m0 = -INFINITY, m1 = -INFINITY, l0 = 0.f, l1 = 0.f;

    // ---- prologue: async-load tiles 0 and 1 ----
    load_tile(0);
    load_tile(1);

#pragma unroll 1
    for (int it = 0; it < NS / 64; it++) {
        const int cur = it % 3;
        // tile `it` complete (groups retire in order; <=1 newer pending)
        if (it < NS / 64 - 1) { CP_WAIT1(); } else { CP_WAIT0(); }
        // barrier + mask check; also fences readers of buf (it-1)%3
        int any = __syncthreads_or((tid < 16) ? (int)(Mw[cur * 16 + tid] != 0u) : 0);
        // prefetch tile it+2 into buf (it+2)%3 == (it-1)%3 (safe post-barrier)
        if (it + 2 < NS / 64) load_tile(it + 2);

        const __half* Kcur = Ksm + cur * AT_TILE;
        const __half* Vcur = Vsm + cur * AT_TILE;

        // ---- QK^T via ldmatrix(non-trans) B-frags ----
        float D[8][4];
#pragma unroll
        for (int nb = 0; nb < 8; nb++) {
            D[nb][0] = 0.f; D[nb][1] = 0.f; D[nb][2] = 0.f; D[nb][3] = 0.f;
        }
#pragma unroll
        for (int kc = 0; kc < 4; kc++) {
#pragma unroll
            for (int nbp = 0; nbp < 4; nbp++) {
                int row = nbp * 16 + ((lane >> 4) & 1) * 8 + (lane & 7);
                int col = kc * 16 + ((lane >> 3) & 1) * 8;
                uint32_t bf[4];
                ldsm4(bf, cvta_s(Kcur + row * 72 + col));
                mma_f16(D[2 * nbp],     Qf[kc], bf[0], bf[1]);
                mma_f16(D[2 * nbp + 1], Qf[kc], bf[2], bf[3]);
            }
        }

        // ---- mask (fast path skips when tile unmasked) ----
        if (any) {
            const unsigned char* Msk = (const unsigned char*)(Mw + cur * 16);
#pragma unroll
            for (int nb = 0; nb < 8; nb++) {
                int c0 = nb * 8 + 2 * q;
                if (Msk[c0])     { D[nb][0] = -INFINITY; D[nb][2] = -INFINITY; }
                if (Msk[c0 + 1]) { D[nb][1] = -INFINITY; D[nb][3] = -INFINITY; }
            }
        }

        // ---- online softmax (log2 domain); rows g, g+8 ----
        float ml0 = -INFINITY, ml1 = -INFINITY;
#pragma unroll
        for (int nb = 0; nb < 8; nb++) {
            ml0 = fmaxf(ml0, fmaxf(D[nb][0], D[nb][1]));
            ml1 = fmaxf(ml1, fmaxf(D[nb][2], D[nb][3]));
        }
        ml0 = fmaxf(ml0, __shfl_xor_sync(0xffffffffu, ml0, 1));
        ml0 = fmaxf(ml0, __shfl_xor_sync(0xffffffffu, ml0, 2));
        ml1 = fmaxf(ml1, __shfl_xor_sync(0xffffffffu, ml1, 1));
        ml1 = fmaxf(ml1, __shfl_xor_sync(0xffffffffu, ml1, 2));

        float mn0 = fmaxf(m0, ml0), mn1 = fmaxf(m1, ml1);
        float ms0 = (mn0 == -INFINITY) ? 0.f : mn0;
        float ms1 = (mn1 == -INFINITY) ? 0.f : mn1;
#pragma unroll
        for (int nb = 0; nb < 8; nb++) {
            D[nb][0] = ex2f(D[nb][0] - ms0);
            D[nb][1] = ex2f(D[nb][1] - ms0);
            D[nb][2] = ex2f(D[nb][2] - ms1);
            D[nb][3] = ex2f(D[nb][3] - ms1);
        }

        float f0 = ex2f(m0 - ms0);   // exact 1.0 when max unchanged
        float f1 = ex2f(m1 - ms1);
        if (ml0 > m0 || ml1 > m1) {  // rescale only when a max moved
#pragma unroll
            for (int nb = 0; nb < 8; nb++) {
                O[nb][0] *= f0; O[nb][1] *= f0;
                O[nb][2] *= f1; O[nb][3] *= f1;
            }
        }
        m0 = mn0; m1 = mn1;

        // ---- O += P @ V ; row sums via P @ ones ----
        float Ssum[4] = {0.f, 0.f, 0.f, 0.f};
#pragma unroll
        for (int kk = 0; kk < 4; kk++) {
            uint32_t a[4];
            a[0] = packh2(D[2 * kk][0],     D[2 * kk][1]);
            a[1] = packh2(D[2 * kk][2],     D[2 * kk][3]);
            a[2] = packh2(D[2 * kk + 1][0], D[2 * kk + 1][1]);
            a[3] = packh2(D[2 * kk + 1][2], D[2 * kk + 1][3]);
            mma_f16(Ssum, a, ONES, ONES);
#pragma unroll
            for (int nbp = 0; nbp < 4; nbp++) {
                int row = kk * 16 + ((lane >> 3) & 1) * 8 + (lane & 7);
                int col = nbp * 16 + ((lane >> 4) & 1) * 8;
                uint32_t bf[4];
                ldsm4t(bf, cvta_s(Vcur + row * 72 + col));
                mma_f16(O[2 * nbp],     a, bf[0], bf[1]);
                mma_f16(O[2 * nbp + 1], a, bf[2], bf[3]);
            }
        }
        l0 = l0 * f0 + Ssum[0];
        l1 = l1 * f1 + Ssum[2];
        // no trailing barrier: next iteration's __syncthreads_or covers it
    }

    // ---- epilogue: normalize, emit hi/lo fp16 split at [B*T, D] ----
    {
        float inv0 = (l0 > 0.f) ? (1.0f / l0) : 0.f;
        float inv1 = (l1 > 0.f) ? (1.0f / l1) : 0.f;
        size_t r0 = ((size_t)(b * NT + t0 + w16 + g))     * ND + h * NHD;
        size_t r1 = ((size_t)(b * NT + t0 + w16 + g + 8)) * ND + h * NHD;
#pragma unroll
        for (int nb = 0; nb < 8; nb++) {
            int c = nb * 8 + 2 * q;
            float x0 = O[nb][0] * inv0, x1 = O[nb][1] * inv0;
            float x2 = O[nb][2] * inv1, x3 = O[nb][3] * inv1;
            __half h0 = __float2half_rn(x0), h1 = __float2half_rn(x1);
            __half h2 = __float2half_rn(x2), h3 = __float2half_rn(x3);
            *(__half2*)&outh[r0 + c] = __halves2half2(h0, h1);
            *(__half2*)&outh[r1 + c] = __halves2half2(h2, h3);
            *(__half2*)&outl[r0 + c] = __floats2half2_rn(
                x0 - __half2float(h0), x1 - __half2float(h1));
            *(__half2*)&outl[r1 + c] = __floats2half2_rn(
                x2 - __half2float(h2), x3 - __half2float(h3));
        }
    }
}

// ---------------------------------------------------------------------------
extern "C" void kernel_launch(void* const* d_in, const int* in_sizes, int n_in,
                              void* d_out, int out_size)
{
    const float* query = (const float*)d_in[0];
    const float* key   = (const float*)d_in[1];
    const float* value = (const float*)d_in[2];
    const unsigned char* mask = (const unsigned char*)d_in[3];
    const float* Wq = (const float*)d_in[4];
    const float* bq = (const float*)d_in[5];
    const float* Wk = (const float*)d_in[6];
    const float* bk = (const float*)d_in[7];
    const float* Wv = (const float*)d_in[8];
    const float* bv = (const float*)d_in[9];
    const float* Wo = (const float*)d_in[10];
    const float* bo = (const float*)d_in[11];
    float* out = (float*)d_out;

    __half *qb, *kb, *vb, *ah, *al, *wh, *wl, *oh, *ol;
    cudaGetSymbolAddress((void**)&qb, g_q);
    cudaGetSymbolAddress((void**)&kb, g_k);
    cudaGetSymbolAddress((void**)&vb, g_v);
    cudaGetSymbolAddress((void**)&ah, g_ah);
    cudaGetSymbolAddress((void**)&al, g_al);
    cudaGetSymbolAddress((void**)&wh, g_wh);
    cudaGetSymbolAddress((void**)&wl, g_wl);
    cudaGetSymbolAddress((void**)&oh, g_oh);
    cudaGetSymbolAddress((void**)&ol, g_ol);

    const int smem3 = G2_ST * 2 * (int)sizeof(__half);   // 61440 B
    cudaFuncSetAttribute(gemm3_kernel,
                         cudaFuncAttributeMaxDynamicSharedMemorySize, smem3);
    cudaFuncSetAttribute(attn_kernel,
                         cudaFuncAttributeMaxDynamicSharedMemorySize, AT_SMEM);

    const int NW = ND * ND;               // 262144 per weight
    const int NA = NB * NT * ND;          // 8388608 per activation

    // fused splits: one launch for 4 weights, one for 3 activations
    split4_kernel<<<dim3(NW / 1024, 4), 256>>>(Wq, Wk, Wv, Wo, wh, wl, NW);
    split4_kernel<<<dim3(NA / 1024, 3), 256>>>(query, key, value, query,
                                               ah, al, NA);

    dim3 gg(ND / 64, (NB * NT) / 128);    // (8, 128)
    gemm3_kernel<<<gg, 256, smem3>>>(ah + 0L * NA, al + 0L * NA,
                                     wh + 0 * NW, wl + 0 * NW, bq, qb, 1);
    gemm3_kernel<<<gg, 256, smem3>>>(ah + 1L * NA, al + 1L * NA,
                                     wh + 1 * NW, wl + 1 * NW, bk, kb, 1);
    gemm3_kernel<<<gg, 256, smem3>>>(ah + 2L * NA, al + 2L * NA,
                                     wh + 2 * NW, wl + 2 * NW, bv, vb, 1);

    dim3 ga(NT / 64, NH, NB);             // (64, 8, 4)
    attn_kernel<<<ga, 128, AT_SMEM>>>(qb, kb, vb, mask, oh, ol);

    gemm3_kernel<<<gg, 256, smem3>>>(oh, ol, wh + 3 * NW, wl + 3 * NW,
                                     bo, out, 0);
}

// round 12
// speedup vs baseline: 1.2713x; 1.0042x over previous
#include <cuda_runtime.h>
#include <cuda_fp16.h>
#include <math.h>
#include <stdint.h>

#define NB 4
#define NT 4096
#define NS 4096
#define ND 512
#define NH 8
#define NHD 64

// Scratch (allocation-free rule: __device__ globals)
__device__ __half g_q[NB * NH * NT * NHD];
__device__ __half g_k[NB * NH * NS * NHD];
__device__ __half g_v[NB * NH * NS * NHD];
__device__ __half g_ah[3 * NB * NT * ND];   // hi split of query|key|value
__device__ __half g_al[3 * NB * NT * ND];   // lo split
__device__ __half g_wh[4 * ND * ND];        // hi split of Wq|Wk|Wv|Wo
__device__ __half g_wl[4 * ND * ND];
__device__ __half g_oh[NB * NT * ND];       // hi split of attention output
__device__ __half g_ol[NB * NT * ND];

// ===========================================================================
// helpers
// ===========================================================================
__device__ __forceinline__ float ex2f(float x) {
    float y;
    asm("ex2.approx.ftz.f32 %0, %1;" : "=f"(y) : "f"(x));
    return y;
}
__device__ __forceinline__ uint32_t h2ex2(uint32_t x) {   // packed fp16x2 2^x
    uint32_t y;
    asm("ex2.approx.f16x2 %0, %1;" : "=r"(y) : "r"(x));
    return y;
}
__device__ __forceinline__ uint32_t packh2(float lo, float hi) {
    __half2 h = __floats2half2_rn(lo, hi);
    return *reinterpret_cast<uint32_t*>(&h);
}
__device__ __forceinline__ uint32_t cvta_s(const void* p) {
    return (uint32_t)__cvta_generic_to_shared(p);
}
// D += A * B  (m16n8k16 fp16 in, fp32 accum; A row-major, B col-major)
__device__ __forceinline__ void mma_f16(float* d, const uint32_t* a,
                                        uint32_t b0, uint32_t b1) {
    asm volatile(
        "mma.sync.aligned.m16n8k16.row.col.f32.f16.f16.f32 "
        "{%0,%1,%2,%3}, {%4,%5,%6,%7}, {%8,%9}, {%0,%1,%2,%3};"
        : "+f"(d[0]), "+f"(d[1]), "+f"(d[2]), "+f"(d[3])
        : "r"(a[0]), "r"(a[1]), "r"(a[2]), "r"(a[3]), "r"(b0), "r"(b1));
}
__device__ __forceinline__ void ldsm4(uint32_t* r, uint32_t addr) {
    asm volatile("ldmatrix.sync.aligned.m8n8.x4.shared.b16 {%0,%1,%2,%3}, [%4];"
                 : "=r"(r[0]), "=r"(r[1]), "=r"(r[2]), "=r"(r[3]) : "r"(addr));
}
__device__ __forceinline__ void ldsm4t(uint32_t* r, uint32_t addr) {
    asm volatile("ldmatrix.sync.aligned.m8n8.x4.trans.shared.b16 {%0,%1,%2,%3}, [%4];"
                 : "=r"(r[0]), "=r"(r[1]), "=r"(r[2]), "=r"(r[3]) : "r"(addr));
}
__device__ __forceinline__ void cp16(uint32_t dst, const void* src) {
    asm volatile("cp.async.cg.shared.global [%0], [%1], 16;" :: "r"(dst), "l"(src));
}
#define CP_COMMIT() asm volatile("cp.async.commit_group;")
#define CP_WAIT1()  asm volatile("cp.async.wait_group 1;")
#define CP_WAIT0()  asm volatile("cp.async.wait_group 0;")

// ---------------------------------------------------------------------------
// fused split: fp32 -> (hi, lo) fp16; blockIdx.y selects one of <=4 tensors
// ---------------------------------------------------------------------------
__global__ __launch_bounds__(256)
void split4_kernel(const float* __restrict__ i0, const float* __restrict__ i1,
                   const float* __restrict__ i2, const float* __restrict__ i3,
                   __half* __restrict__ hi, __half* __restrict__ lo, int n)
{
    const float* in = (blockIdx.y == 0) ? i0 : (blockIdx.y == 1) ? i1
                    : (blockIdx.y == 2) ? i2 : i3;
    const size_t off = (size_t)blockIdx.y * n;
    int i = (blockIdx.x * 256 + threadIdx.x) * 4;
    if (i >= n) return;
    float4 v = *(const float4*)(in + i);
    __half h[4], l[4];
    h[0] = __float2half_rn(v.x); l[0] = __float2half_rn(v.x - __half2float(h[0]));
    h[1] = __float2half_rn(v.y); l[1] = __float2half_rn(v.y - __half2float(h[1]));
    h[2] = __float2half_rn(v.z); l[2] = __float2half_rn(v.z - __half2float(h[2]));
    h[3] = __float2half_rn(v.w); l[3] = __float2half_rn(v.w - __half2float(h[3]));
    *(uint2*)(hi + off + i) = *(uint2*)h;
    *(uint2*)(lo + off + i) = *(uint2*)l;
}

// ---------------------------------------------------------------------------
// 3-term split-fp16 GEMM core (R10 schedule, proven). When FUSED_QKV, the
// launch covers all three projections via blockIdx.z (wave-quantization fix:
// 3072 tiles in one launch = 7 wave-times vs 9 across three launches).
// ---------------------------------------------------------------------------
#define G2_AH 0                       // offsets in halves within a stage
#define G2_AL (128 * 40)
#define G2_WH (2 * 128 * 40)
#define G2_WL (2 * 128 * 40 + 64 * 40)
#define G2_ST (2 * 128 * 40 + 2 * 64 * 40)   // 15360 halves per stage

template <int FUSED_QKV>
__device__ __forceinline__
void gemm3_body(const __half* Ah, const __half* Al,
                const __half* Wh, const __half* Wl,
                const float* bias, void* outp, int head_layout)
{
    extern __shared__ __half dsm[];

    const int tid  = threadIdx.x;
    const int warp = tid >> 5, lane = tid & 31;
    const int g = lane >> 2, q = lane & 3;
    const int m0 = blockIdx.y * 128;
    const int n0 = blockIdx.x * 64;

    const int arow = tid >> 1, acb = (tid & 1) * 16;
    const int wrow = tid >> 2, wcb = (tid & 3) * 8;

    const __half* Agh = Ah + (size_t)(m0 + arow) * ND + acb;
    const __half* Agl = Al + (size_t)(m0 + arow) * ND + acb;
    const __half* Wgh = Wh + (size_t)(n0 + wrow) * ND + wcb;
    const __half* Wgl = Wl + (size_t)(n0 + wrow) * ND + wcb;

    float D[8][4];
#pragma unroll
    for (int nb = 0; nb < 8; nb++)
#pragma unroll
        for (int i = 0; i < 4; i++) D[nb][i] = 0.f;

    auto load_stage = [&](int stage, int k0) {
        __half* base = dsm + (stage & 1) * G2_ST;
        uint32_t ah = cvta_s(base + G2_AH + arow * 40 + acb);
        uint32_t al = cvta_s(base + G2_AL + arow * 40 + acb);
        uint32_t wh = cvta_s(base + G2_WH + wrow * 40 + wcb);
        uint32_t wl = cvta_s(base + G2_WL + wrow * 40 + wcb);
#pragma unroll
        for (int j = 0; j < 2; j++) {
            cp16(ah + j * 16, Agh + k0 + j * 8);
            cp16(al + j * 16, Agl + k0 + j * 8);
        }
        cp16(wh, Wgh + k0);
        cp16(wl, Wgl + k0);
        CP_COMMIT();
    };

    load_stage(0, 0);
    load_stage(1, 32);

#pragma unroll 1
    for (int it = 0; it < ND / 32; it++) {
        const __half* base = dsm + (it & 1) * G2_ST;

        if (it < ND / 32 - 1) { CP_WAIT1(); } else { CP_WAIT0(); }
        __syncthreads();

#pragma unroll
        for (int kc = 0; kc < 2; kc++) {
            int arw = warp * 16 + (lane & 15);
            int acl = kc * 16 + (lane >> 4) * 8;
            uint32_t ahf[4], alf[4];
            ldsm4(ahf, cvta_s(base + G2_AH + arw * 40 + acl));
            ldsm4(alf, cvta_s(base + G2_AL + arw * 40 + acl));
#pragma unroll
            for (int nbp = 0; nbp < 4; nbp++) {
                int row = nbp * 16 + ((lane >> 4) & 1) * 8 + (lane & 7);
                int col = kc * 16 + ((lane >> 3) & 1) * 8;
                uint32_t bh[4], bl[4];
                ldsm4(bh, cvta_s(base + G2_WH + row * 40 + col));
                ldsm4(bl, cvta_s(base + G2_WL + row * 40 + col));
                mma_f16(D[2 * nbp],     ahf, bh[0], bh[1]);
                mma_f16(D[2 * nbp + 1], ahf, bh[2], bh[3]);
                mma_f16(D[2 * nbp],     alf, bh[0], bh[1]);
                mma_f16(D[2 * nbp + 1], alf, bh[2], bh[3]);
                mma_f16(D[2 * nbp],     ahf, bl[0], bl[1]);
                mma_f16(D[2 * nbp + 1], ahf, bl[2], bl[3]);
            }
        }
        __syncthreads();
        if (it + 2 < ND / 32) load_stage(it + 2, (it + 2) * 32);
    }

    // ---- epilogue ----
    const float* bp = bias + n0;
    const int mg = m0 + warp * 16 + g;
#pragma unroll
    for (int nb = 0; nb < 8; nb++) {
        int c = nb * 8 + 2 * q;
        float2 bb = *(const float2*)(bp + c);
        float o00 = D[nb][0] + bb.x, o01 = D[nb][1] + bb.y;   // row mg
        float o10 = D[nb][2] + bb.x, o11 = D[nb][3] + bb.y;   // row mg+8
        if (head_layout) {
            int h = n0 >> 6;
            int bbi = mg >> 12, t = mg & 4095;
            __half* oh = (__half*)outp;
            size_t bse = ((size_t)(bbi * NH + h) * NT + t) * NHD + c;
            *(__half2*)&oh[bse]           = __floats2half2_rn(o00, o01);
            *(__half2*)&oh[bse + 8 * NHD] = __floats2half2_rn(o10, o11);
        } else {
            float* of = (float*)outp;
            size_t bse = (size_t)mg * ND + n0 + c;
            *(float2*)&of[bse]          = make_float2(o00, o01);
            *(float2*)&of[bse + 8 * ND] = make_float2(o10, o11);
        }
    }
}

// fused QKV projections: blockIdx.z selects (activation, weight, bias, out)
__global__ __launch_bounds__(256, 3)
void gemmqkv_kernel(const __half* __restrict__ ah, const __half* __restrict__ al,
                    const __half* __restrict__ wh, const __half* __restrict__ wl,
                    const float* __restrict__ bq, const float* __restrict__ bk,
                    const float* __restrict__ bv,
                    __half* __restrict__ qb, __half* __restrict__ kb,
                    __half* __restrict__ vb)
{
    const int z = blockIdx.z;
    const size_t NAo = (size_t)NB * NT * ND;
    const size_t NWo = (size_t)ND * ND;
    const float* bias = (z == 0) ? bq : (z == 1) ? bk : bv;
    __half* outp = (z == 0) ? qb : (z == 1) ? kb : vb;
    gemm3_body<1>(ah + z * NAo, al + z * NAo, wh + z * NWo, wl + z * NWo,
                  bias, outp, 1);
}

// single GEMM (used for the Wo projection, fp32 output)
__global__ __launch_bounds__(256, 3)
void gemm3_kernel(const __half* __restrict__ Ah, const __half* __restrict__ Al,
                  const __half* __restrict__ Wh, const __half* __restrict__ Wl,
                  const float* __restrict__ bias, void* __restrict__ outp,
                  int head_layout)
{
    gemm3_body<0>(Ah, Al, Wh, Wl, bias, outp, head_layout);
}

// ---------------------------------------------------------------------------
// fp16 flash attention v7: v6 ring-buffer schedule + P exponential computed
// with ex2.approx.f16x2 (halves MUFU pressure; P was rounded to fp16 for the
// PV mma anyway, so the arithmetic change is ~1 ulp fp16 on P).
// ---------------------------------------------------------------------------
#define AT_TILE (64 * 72)                       // halves per K or V buffer
#define AT_MSK  (6 * AT_TILE)                   // mask offset (halves)
#define AT_SMEM (6 * AT_TILE * 2 + 3 * 64)      // bytes: 55296 + 192

__global__ __launch_bounds__(128)
void attn_kernel(const __half* __restrict__ Qh, const __half* __restrict__ Kh,
                 const __half* __restrict__ Vh,
                 const unsigned char* __restrict__ mask,
                 __half* __restrict__ outh, __half* __restrict__ outl)
{
    extern __shared__ __half asmem[];
    __half* Ksm = asmem;                 // [3][64][72]
    __half* Vsm = asmem + 3 * AT_TILE;   // [3][64][72]
    uint32_t* Mw = (uint32_t*)(asmem + AT_MSK);   // [3][16]

    const int b  = blockIdx.z;
    const int h  = blockIdx.y;
    const int t0 = blockIdx.x * 64;
    const int tid  = threadIdx.x;
    const int warp = tid >> 5;
    const int lane = tid & 31;
    const int g = lane >> 2;
    const int q = lane & 3;
    const int w16 = warp * 16;
    const uint32_t ONES = 0x3C003C00u;   // half2(1,1)

    const __half* Kp = Kh + (size_t)(b * NH + h) * NS * NHD;
    const __half* Vp = Vh + (size_t)(b * NH + h) * NS * NHD;
    const unsigned char* mp = mask + (size_t)b * NS;

    const int lrow = tid >> 1;
    const int lcol = (tid & 1) * 32;

    auto load_tile = [&](int t) {
        int buf = t % 3;
        const __half* kg = Kp + (size_t)(t * 64 + lrow) * NHD + lcol;
        const __half* vg = Vp + (size_t)(t * 64 + lrow) * NHD + lcol;
        uint32_t kd = cvta_s(Ksm + buf * AT_TILE + lrow * 72 + lcol);
        uint32_t vd = cvta_s(Vsm + buf * AT_TILE + lrow * 72 + lcol);
#pragma unroll
        for (int j = 0; j < 4; j++) {
            cp16(kd + j * 16, kg + j * 8);
            cp16(vd + j * 16, vg + j * 8);
        }
        if (tid < 4) cp16(cvta_s(Mw + buf * 16 + tid * 4), mp + t * 64 + tid * 16);
        CP_COMMIT();
    };

    // ---- Q fragments (fp16 regs, once), scale 0.125*log2(e) ----
    uint32_t Qf[4][4];
    {
        const __half2 qs2 = __float2half2_rn(0.125f * 1.4426950408889634f);
        const __half* Q0 = Qh + ((size_t)(b * NH + h) * NT + t0 + w16 + g) * NHD;
        const __half* Q1 = Q0 + 8 * NHD;
#pragma unroll
        for (int kc = 0; kc < 4; kc++) {
            __half2 x0 = __hmul2(*(const __half2*)(Q0 + kc * 16 + 2 * q),     qs2);
            __half2 x1 = __hmul2(*(const __half2*)(Q1 + kc * 16 + 2 * q),     qs2);
            __half2 x2 = __hmul2(*(const __half2*)(Q0 + kc * 16 + 2 * q + 8), qs2);
            __half2 x3 = __hmul2(*(const __half2*)(Q1 + kc * 16 + 2 * q + 8), qs2);
            Qf[kc][0] = *(uint32_t*)&x0;
            Qf[kc][1] = *(uint32_t*)&x1;
            Qf[kc][2] = *(uint32_t*)&x2;
            Qf[kc][3] = *(uint32_t*)&x3;
        }
    }

    float O[8][4];
#pragma unroll
    for (int nb = 0; nb < 8; nb++)
#pragma unroll
        for (int i = 0; i < 4; i++) O[nb][i] = 0.f;
    float m0 = -INFINITY, m1 = -INFINITY, l0 = 0.f, l1 = 0.f;

    // ---- prologue: async-load tiles 0 and 1 ----
    load_tile(0);
    load_tile(1);

#pragma unroll 1
    for (int it = 0; it < NS / 64; it++) {
        const int cur = it % 3;
        if (it < NS / 64 - 1) { CP_WAIT1(); } else { CP_WAIT0(); }
        int any = __syncthreads_or((tid < 16) ? (int)(Mw[cur * 16 + tid] != 0u) : 0);
        if (it + 2 < NS / 64) load_tile(it + 2);

        const __half* Kcur = Ksm + cur * AT_TILE;
        const __half* Vcur = Vsm + cur * AT_TILE;

        // ---- QK^T via ldmatrix(non-trans) B-frags ----
        float D[8][4];
#pragma unroll
        for (int nb = 0; nb < 8; nb++) {
            D[nb][0] = 0.f; D[nb][1] = 0.f; D[nb][2] = 0.f; D[nb][3] = 0.f;
        }
#pragma unroll
        for (int kc = 0; kc < 4; kc++) {
#pragma unroll
            for (int nbp = 0; nbp < 4; nbp++) {
                int row = nbp * 16 + ((lane >> 4) & 1) * 8 + (lane & 7);
                int col = kc * 16 + ((lane >> 3) & 1) * 8;
                uint32_t bf[4];
                ldsm4(bf, cvta_s(Kcur + row * 72 + col));
                mma_f16(D[2 * nbp],     Qf[kc], bf[0], bf[1]);
                mma_f16(D[2 * nbp + 1], Qf[kc], bf[2], bf[3]);
            }
        }

        // ---- mask (fast path skips when tile unmasked) ----
        if (any) {
            const unsigned char* Msk = (const unsigned char*)(Mw + cur * 16);
#pragma unroll
            for (int nb = 0; nb < 8; nb++) {
                int c0 = nb * 8 + 2 * q;
                if (Msk[c0])     { D[nb][0] = -INFINITY; D[nb][2] = -INFINITY; }
                if (Msk[c0 + 1]) { D[nb][1] = -INFINITY; D[nb][3] = -INFINITY; }
            }
        }

        // ---- online softmax (log2 domain); rows g, g+8 ----
        float ml0 = -INFINITY, ml1 = -INFINITY;
#pragma unroll
        for (int nb = 0; nb < 8; nb++) {
            ml0 = fmaxf(ml0, fmaxf(D[nb][0], D[nb][1]));
            ml1 = fmaxf(ml1, fmaxf(D[nb][2], D[nb][3]));
        }
        ml0 = fmaxf(ml0, __shfl_xor_sync(0xffffffffu, ml0, 1));
        ml0 = fmaxf(ml0, __shfl_xor_sync(0xffffffffu, ml0, 2));
        ml1 = fmaxf(ml1, __shfl_xor_sync(0xffffffffu, ml1, 1));
        ml1 = fmaxf(ml1, __shfl_xor_sync(0xffffffffu, ml1, 2));

        float mn0 = fmaxf(m0, ml0), mn1 = fmaxf(m1, ml1);
        float ms0 = (mn0 == -INFINITY) ? 0.f : mn0;
        float ms1 = (mn1 == -INFINITY) ? 0.f : mn1;

        // P = 2^(D - ms) computed in packed fp16 (halves MUFU; P is fp16 anyway)
        uint32_t Pa[8], Pb[8];
#pragma unroll
        for (int nb = 0; nb < 8; nb++) {
            Pa[nb] = h2ex2(packh2(D[nb][0] - ms0, D[nb][1] - ms0));
            Pb[nb] = h2ex2(packh2(D[nb][2] - ms1, D[nb][3] - ms1));
        }

        float f0 = ex2f(m0 - ms0);   // exact 1.0 when max unchanged
        float f1 = ex2f(m1 - ms1);
        if (ml0 > m0 || ml1 > m1) {  // rescale only when a max moved
#pragma unroll
            for (int nb = 0; nb < 8; nb++) {
                O[nb][0] *= f0; O[nb][1] *= f0;
                O[nb][2] *= f1; O[nb][3] *= f1;
            }
        }
        m0 = mn0; m1 = mn1;

        // ---- O += P @ V ; row sums via P @ ones ----
        float Ssum[4] = {0.f, 0.f, 0.f, 0.f};
#pragma unroll
        for (int kk = 0; kk < 4; kk++) {
            uint32_t a[4];
            a[0] = Pa[2 * kk];
            a[1] = Pb[2 * kk];
            a[2] = Pa[2 * kk + 1];
            a[3] = Pb[2 * kk + 1];
            mma_f16(Ssum, a, ONES, ONES);
#pragma unroll
            for (int nbp = 0; nbp < 4; nbp++) {
                int row = kk * 16 + ((lane >> 3) & 1) * 8 + (lane & 7);
                int col = nbp * 16 + ((lane >> 4) & 1) * 8;
                uint32_t bf[4];
                ldsm4t(bf, cvta_s(Vcur + row * 72 + col));
                mma_f16(O[2 * nbp],     a, bf[0], bf[1]);
                mma_f16(O[2 * nbp + 1], a, bf[2], bf[3]);
            }
        }
        l0 = l0 * f0 + Ssum[0];
        l1 = l1 * f1 + Ssum[2];
        // no trailing barrier: next iteration's __syncthreads_or covers it
    }

    // ---- epilogue: normalize, emit hi/lo fp16 split at [B*T, D] ----
    {
        float inv0 = (l0 > 0.f) ? (1.0f / l0) : 0.f;
        float inv1 = (l1 > 0.f) ? (1.0f / l1) : 0.f;
        size_t r0 = ((size_t)(b * NT + t0 + w16 + g))     * ND + h * NHD;
        size_t r1 = ((size_t)(b * NT + t0 + w16 + g + 8)) * ND + h * NHD;
#pragma unroll
        for (int nb = 0; nb < 8; nb++) {
            int c = nb * 8 + 2 * q;
            float x0 = O[nb][0] * inv0, x1 = O[nb][1] * inv0;
            float x2 = O[nb][2] * inv1, x3 = O[nb][3] * inv1;
            __half h0 = __float2half_rn(x0), h1 = __float2half_rn(x1);
            __half h2 = __float2half_rn(x2), h3 = __float2half_rn(x3);
            *(__half2*)&outh[r0 + c] = __halves2half2(h0, h1);
            *(__half2*)&outh[r1 + c] = __halves2half2(h2, h3);
            *(__half2*)&outl[r0 + c] = __floats2half2_rn(
                x0 - __half2float(h0), x1 - __half2float(h1));
            *(__half2*)&outl[r1 + c] = __floats2half2_rn(
                x2 - __half2float(h2), x3 - __half2float(h3));
        }
    }
}

// ---------------------------------------------------------------------------
extern "C" void kernel_launch(void* const* d_in, const int* in_sizes, int n_in,
                              void* d_out, int out_size)
{
    const float* query = (const float*)d_in[0];
    const float* key   = (const float*)d_in[1];
    const float* value = (const float*)d_in[2];
    const unsigned char* mask = (const unsigned char*)d_in[3];
    const float* Wq = (const float*)d_in[4];
    const float* bq = (const float*)d_in[5];
    const float* Wk = (const float*)d_in[6];
    const float* bk = (const float*)d_in[7];
    const float* Wv = (const float*)d_in[8];
    const float* bv = (const float*)d_in[9];
    const float* Wo = (const float*)d_in[10];
    const float* bo = (const float*)d_in[11];
    float* out = (float*)d_out;

    __half *qb, *kb, *vb, *ah, *al, *wh, *wl, *oh, *ol;
    cudaGetSymbolAddress((void**)&qb, g_q);
    cudaGetSymbolAddress((void**)&kb, g_k);
    cudaGetSymbolAddress((void**)&vb, g_v);
    cudaGetSymbolAddress((void**)&ah, g_ah);
    cudaGetSymbolAddress((void**)&al, g_al);
    cudaGetSymbolAddress((void**)&wh, g_wh);
    cudaGetSymbolAddress((void**)&wl, g_wl);
    cudaGetSymbolAddress((void**)&oh, g_oh);
    cudaGetSymbolAddress((void**)&ol, g_ol);

    const int smem3 = G2_ST * 2 * (int)sizeof(__half);   // 61440 B
    cudaFuncSetAttribute(gemm3_kernel,
                         cudaFuncAttributeMaxDynamicSharedMemorySize, smem3);
    cudaFuncSetAttribute(gemmqkv_kernel,
                         cudaFuncAttributeMaxDynamicSharedMemorySize, smem3);
    cudaFuncSetAttribute(attn_kernel,
                         cudaFuncAttributeMaxDynamicSharedMemorySize, AT_SMEM);

    const int NW = ND * ND;               // 262144 per weight
    const int NA = NB * NT * ND;          // 8388608 per activation

    // fused splits: one launch for 4 weights, one for 3 activations
    split4_kernel<<<dim3(NW / 1024, 4), 256>>>(Wq, Wk, Wv, Wo, wh, wl, NW);
    split4_kernel<<<dim3(NA / 1024, 3), 256>>>(query, key, value, query,
                                               ah, al, NA);

    // fused QKV projections (one launch, grid.z selects projection)
    dim3 gq(ND / 64, (NB * NT) / 128, 3);   // (8, 128, 3)
    gemmqkv_kernel<<<gq, 256, smem3>>>(ah, al, wh, wl, bq, bk, bv, qb, kb, vb);

    dim3 ga(NT / 64, NH, NB);               // (64, 8, 4)
    attn_kernel<<<ga, 128, AT_SMEM>>>(qb, kb, vb, mask, oh, ol);

    dim3 gg(ND / 64, (NB * NT) / 128);      // (8, 128)
    gemm3_kernel<<<gg, 256, smem3>>>(oh, ol, wh + 3 * NW, wl + 3 * NW,
                                     bo, out, 0);
}

// round 13
// speedup vs baseline: 1.3397x; 1.0538x over previous
#include <cuda_runtime.h>
#include <cuda_fp16.h>
#include <math.h>
#include <stdint.h>

#define NB 4
#define NT 4096
#define NS 4096
#define ND 512
#define NH 8
#define NHD 64

// Scratch (allocation-free rule: __device__ globals)
__device__ __half g_q[NB * NH * NT * NHD];
__device__ __half g_k[NB * NH * NS * NHD];
__device__ __half g_v[NB * NH * NS * NHD];
__device__ __half g_ah[3 * NB * NT * ND];   // hi split of query|key|value
__device__ __half g_al[3 * NB * NT * ND];   // lo split
__device__ __half g_wh[4 * ND * ND];        // hi split of Wq|Wk|Wv|Wo
__device__ __half g_wl[4 * ND * ND];
__device__ __half g_oh[NB * NT * ND];       // attention output (fp16)

// ===========================================================================
// helpers
// ===========================================================================
__device__ __forceinline__ float ex2f(float x) {
    float y;
    asm("ex2.approx.ftz.f32 %0, %1;" : "=f"(y) : "f"(x));
    return y;
}
__device__ __forceinline__ uint32_t packh2(float lo, float hi) {
    __half2 h = __floats2half2_rn(lo, hi);
    return *reinterpret_cast<uint32_t*>(&h);
}
__device__ __forceinline__ uint32_t cvta_s(const void* p) {
    return (uint32_t)__cvta_generic_to_shared(p);
}
// D += A * B  (m16n8k16 fp16 in, fp32 accum; A row-major, B col-major)
__device__ __forceinline__ void mma_f16(float* d, const uint32_t* a,
                                        uint32_t b0, uint32_t b1) {
    asm volatile(
        "mma.sync.aligned.m16n8k16.row.col.f32.f16.f16.f32 "
        "{%0,%1,%2,%3}, {%4,%5,%6,%7}, {%8,%9}, {%0,%1,%2,%3};"
        : "+f"(d[0]), "+f"(d[1]), "+f"(d[2]), "+f"(d[3])
        : "r"(a[0]), "r"(a[1]), "r"(a[2]), "r"(a[3]), "r"(b0), "r"(b1));
}
__device__ __forceinline__ void ldsm4(uint32_t* r, uint32_t addr) {
    asm volatile("ldmatrix.sync.aligned.m8n8.x4.shared.b16 {%0,%1,%2,%3}, [%4];"
                 : "=r"(r[0]), "=r"(r[1]), "=r"(r[2]), "=r"(r[3]) : "r"(addr));
}
__device__ __forceinline__ void ldsm4t(uint32_t* r, uint32_t addr) {
    asm volatile("ldmatrix.sync.aligned.m8n8.x4.trans.shared.b16 {%0,%1,%2,%3}, [%4];"
                 : "=r"(r[0]), "=r"(r[1]), "=r"(r[2]), "=r"(r[3]) : "r"(addr));
}
__device__ __forceinline__ void cp16(uint32_t dst, const void* src) {
    asm volatile("cp.async.cg.shared.global [%0], [%1], 16;" :: "r"(dst), "l"(src));
}
#define CP_COMMIT() asm volatile("cp.async.commit_group;")
#define CP_WAIT1()  asm volatile("cp.async.wait_group 1;")
#define CP_WAIT0()  asm volatile("cp.async.wait_group 0;")

// ---------------------------------------------------------------------------
// fused split: fp32 -> (hi, lo) fp16; blockIdx.y selects one of <=4 tensors
// ---------------------------------------------------------------------------
__global__ __launch_bounds__(256)
void split4_kernel(const float* __restrict__ i0, const float* __restrict__ i1,
                   const float* __restrict__ i2, const float* __restrict__ i3,
                   __half* __restrict__ hi, __half* __restrict__ lo, int n)
{
    const float* in = (blockIdx.y == 0) ? i0 : (blockIdx.y == 1) ? i1
                    : (blockIdx.y == 2) ? i2 : i3;
    const size_t off = (size_t)blockIdx.y * n;
    int i = (blockIdx.x * 256 + threadIdx.x) * 4;
    if (i >= n) return;
    float4 v = *(const float4*)(in + i);
    __half h[4], l[4];
    h[0] = __float2half_rn(v.x); l[0] = __float2half_rn(v.x - __half2float(h[0]));
    h[1] = __float2half_rn(v.y); l[1] = __float2half_rn(v.y - __half2float(h[1]));
    h[2] = __float2half_rn(v.z); l[2] = __float2half_rn(v.z - __half2float(h[2]));
    h[3] = __float2half_rn(v.w); l[3] = __float2half_rn(v.w - __half2float(h[3]));
    *(uint2*)(hi + off + i) = *(uint2*)h;
    *(uint2*)(lo + off + i) = *(uint2*)l;
}

// ---------------------------------------------------------------------------
// split-fp16 GEMM core (R10 schedule, proven). USE_AL=1: 3-term
// (Ah*Wh + Al*Wh + Ah*Wl); USE_AL=0: 2-term (Ah*Wh + Ah*Wl) for fp16 A.
// ---------------------------------------------------------------------------
#define G2_AH 0                       // offsets in halves within a stage
#define G2_AL (128 * 40)
#define G2_WH (2 * 128 * 40)
#define G2_WL (2 * 128 * 40 + 64 * 40)
#define G2_ST (2 * 128 * 40 + 2 * 64 * 40)   // 15360 halves per stage

template <int USE_AL>
__device__ __forceinline__
void gemm3_body(const __half* Ah, const __half* Al,
                const __half* Wh, const __half* Wl,
                const float* bias, void* outp, int head_layout)
{
    extern __shared__ __half dsm[];

    const int tid  = threadIdx.x;
    const int warp = tid >> 5, lane = tid & 31;
    const int g = lane >> 2, q = lane & 3;
    const int m0 = blockIdx.y * 128;
    const int n0 = blockIdx.x * 64;

    const int arow = tid >> 1, acb = (tid & 1) * 16;
    const int wrow = tid >> 2, wcb = (tid & 3) * 8;

    const __half* Agh = Ah + (size_t)(m0 + arow) * ND + acb;
    const __half* Agl = Al + (size_t)(m0 + arow) * ND + acb;
    const __half* Wgh = Wh + (size_t)(n0 + wrow) * ND + wcb;
    const __half* Wgl = Wl + (size_t)(n0 + wrow) * ND + wcb;

    float D[8][4];
#pragma unroll
    for (int nb = 0; nb < 8; nb++)
#pragma unroll
        for (int i = 0; i < 4; i++) D[nb][i] = 0.f;

    auto load_stage = [&](int stage, int k0) {
        __half* base = dsm + (stage & 1) * G2_ST;
        uint32_t ah = cvta_s(base + G2_AH + arow * 40 + acb);
        uint32_t wh = cvta_s(base + G2_WH + wrow * 40 + wcb);
        uint32_t wl = cvta_s(base + G2_WL + wrow * 40 + wcb);
#pragma unroll
        for (int j = 0; j < 2; j++)
            cp16(ah + j * 16, Agh + k0 + j * 8);
        if (USE_AL) {
            uint32_t al = cvta_s(base + G2_AL + arow * 40 + acb);
#pragma unroll
            for (int j = 0; j < 2; j++)
                cp16(al + j * 16, Agl + k0 + j * 8);
        }
        cp16(wh, Wgh + k0);
        cp16(wl, Wgl + k0);
        CP_COMMIT();
    };

    load_stage(0, 0);
    load_stage(1, 32);

#pragma unroll 1
    for (int it = 0; it < ND / 32; it++) {
        const __half* base = dsm + (it & 1) * G2_ST;

        if (it < ND / 32 - 1) { CP_WAIT1(); } else { CP_WAIT0(); }
        __syncthreads();

#pragma unroll
        for (int kc = 0; kc < 2; kc++) {
            int arw = warp * 16 + (lane & 15);
            int acl = kc * 16 + (lane >> 4) * 8;
            uint32_t ahf[4], alf[4];
            ldsm4(ahf, cvta_s(base + G2_AH + arw * 40 + acl));
            if (USE_AL)
                ldsm4(alf, cvta_s(base + G2_AL + arw * 40 + acl));
#pragma unroll
            for (int nbp = 0; nbp < 4; nbp++) {
                int row = nbp * 16 + ((lane >> 4) & 1) * 8 + (lane & 7);
                int col = kc * 16 + ((lane >> 3) & 1) * 8;
                uint32_t bh[4], bl[4];
                ldsm4(bh, cvta_s(base + G2_WH + row * 40 + col));
                ldsm4(bl, cvta_s(base + G2_WL + row * 40 + col));
                mma_f16(D[2 * nbp],     ahf, bh[0], bh[1]);
                mma_f16(D[2 * nbp + 1], ahf, bh[2], bh[3]);
                if (USE_AL) {
                    mma_f16(D[2 * nbp],     alf, bh[0], bh[1]);
                    mma_f16(D[2 * nbp + 1], alf, bh[2], bh[3]);
                }
                mma_f16(D[2 * nbp],     ahf, bl[0], bl[1]);
                mma_f16(D[2 * nbp + 1], ahf, bl[2], bl[3]);
            }
        }
        __syncthreads();
        if (it + 2 < ND / 32) load_stage(it + 2, (it + 2) * 32);
    }

    // ---- epilogue ----
    const float* bp = bias + n0;
    const int mg = m0 + warp * 16 + g;
#pragma unroll
    for (int nb = 0; nb < 8; nb++) {
        int c = nb * 8 + 2 * q;
        float2 bb = *(const float2*)(bp + c);
        float o00 = D[nb][0] + bb.x, o01 = D[nb][1] + bb.y;   // row mg
        float o10 = D[nb][2] + bb.x, o11 = D[nb][3] + bb.y;   // row mg+8
        if (head_layout) {
            int h = n0 >> 6;
            int bbi = mg >> 12, t = mg & 4095;
            __half* oh = (__half*)outp;
            size_t bse = ((size_t)(bbi * NH + h) * NT + t) * NHD + c;
            *(__half2*)&oh[bse]           = __floats2half2_rn(o00, o01);
            *(__half2*)&oh[bse + 8 * NHD] = __floats2half2_rn(o10, o11);
        } else {
            float* of = (float*)outp;
            size_t bse = (size_t)mg * ND + n0 + c;
            *(float2*)&of[bse]          = make_float2(o00, o01);
            *(float2*)&of[bse + 8 * ND] = make_float2(o10, o11);
        }
    }
}

// fused QKV projections: blockIdx.z selects (activation, weight, bias, out)
__global__ __launch_bounds__(256, 3)
void gemmqkv_kernel(const __half* __restrict__ ah, const __half* __restrict__ al,
                    const __half* __restrict__ wh, const __half* __restrict__ wl,
                    const float* __restrict__ bq, const float* __restrict__ bk,
                    const float* __restrict__ bv,
                    __half* __restrict__ qb, __half* __restrict__ kb,
                    __half* __restrict__ vb)
{
    const int z = blockIdx.z;
    const size_t NAo = (size_t)NB * NT * ND;
    const size_t NWo = (size_t)ND * ND;
    const float* bias = (z == 0) ? bq : (z == 1) ? bk : bv;
    __half* outp = (z == 0) ? qb : (z == 1) ? kb : vb;
    gemm3_body<1>(ah + z * NAo, al + z * NAo, wh + z * NWo, wl + z * NWo,
                  bias, outp, 1);
}

// Wo projection: A is plain fp16 (attention output) -> 2-term GEMM
__global__ __launch_bounds__(256, 3)
void gemmwo_kernel(const __half* __restrict__ Ah,
                   const __half* __restrict__ Wh, const __half* __restrict__ Wl,
                   const float* __restrict__ bias, float* __restrict__ outp)
{
    gemm3_body<0>(Ah, Ah, Wh, Wl, bias, outp, 0);
}

// ---------------------------------------------------------------------------
// fp16 flash attention v8: v6 ring-buffer schedule, fp32 ex2 (margin), mask
// handled via a precomputed per-CTA 64-bit tile bitmask (plain barrier in the
// hot loop; rare masked tiles read mask bytes straight from gmem).
// Output: plain fp16 at [B*T, D] (consumed by the 2-term Wo GEMM).
// ---------------------------------------------------------------------------
#define AT_TILE (64 * 72)                 // halves per K or V buffer
#define AT_SMEM (6 * AT_TILE * 2)         // bytes: 55296

__global__ __launch_bounds__(128)
void attn_kernel(const __half* __restrict__ Qh, const __half* __restrict__ Kh,
                 const __half* __restrict__ Vh,
                 const unsigned char* __restrict__ mask,
                 __half* __restrict__ outh)
{
    extern __shared__ __half asmem[];
    __half* Ksm = asmem;                 // [3][64][72]
    __half* Vsm = asmem + 3 * AT_TILE;   // [3][64][72]

    const int b  = blockIdx.z;
    const int h  = blockIdx.y;
    const int t0 = blockIdx.x * 64;
    const int tid  = threadIdx.x;
    const int warp = tid >> 5;
    const int lane = tid & 31;
    const int g = lane >> 2;
    const int q = lane & 3;
    const int w16 = warp * 16;
    const uint32_t ONES = 0x3C003C00u;   // half2(1,1)

    const __half* Kp = Kh + (size_t)(b * NH + h) * NS * NHD;
    const __half* Vp = Vh + (size_t)(b * NH + h) * NS * NHD;
    const unsigned char* mp = mask + (size_t)b * NS;

    const int lrow = tid >> 1;
    const int lcol = (tid & 1) * 32;

    auto load_tile = [&](int t) {
        int buf = t % 3;
        const __half* kg = Kp + (size_t)(t * 64 + lrow) * NHD + lcol;
        const __half* vg = Vp + (size_t)(t * 64 + lrow) * NHD + lcol;
        uint32_t kd = cvta_s(Ksm + buf * AT_TILE + lrow * 72 + lcol);
        uint32_t vd = cvta_s(Vsm + buf * AT_TILE + lrow * 72 + lcol);
#pragma unroll
        for (int j = 0; j < 4; j++) {
            cp16(kd + j * 16, kg + j * 8);
            cp16(vd + j * 16, vg + j * 8);
        }
        CP_COMMIT();
    };

    // ---- per-CTA 64-bit "tile has masked column" bitmask (computed once) ---
    uint64_t mbits;
    {
        const uint4* mq = (const uint4*)mp;          // 4096 B = 256 uint4
        uint4 a = mq[2 * tid], c = mq[2 * tid + 1];  // 32 B per thread
        uint32_t o = a.x | a.y | a.z | a.w | c.x | c.y | c.z | c.w;
        uint32_t bal = __ballot_sync(0xffffffffu, o != 0u);
        uint32_t t16 = 0;
#pragma unroll
        for (int j = 0; j < 16; j++)
            t16 |= (((bal >> (2 * j)) & 3u) ? 1u : 0u) << j;
        __shared__ uint32_t wbits[4];
        if (lane == 0) wbits[warp] = t16;
        __syncthreads();
        mbits = (uint64_t)wbits[0] | ((uint64_t)wbits[1] << 16)
              | ((uint64_t)wbits[2] << 32) | ((uint64_t)wbits[3] << 48);
    }

    // ---- Q fragments (fp16 regs, once), scale 0.125*log2(e) ----
    uint32_t Qf[4][4];
    {
        const __half2 qs2 = __float2half2_rn(0.125f * 1.4426950408889634f);
        const __half* Q0 = Qh + ((size_t)(b * NH + h) * NT + t0 + w16 + g) * NHD;
        const __half* Q1 = Q0 + 8 * NHD;
#pragma unroll
        for (int kc = 0; kc < 4; kc++) {
            __half2 x0 = __hmul2(*(const __half2*)(Q0 + kc * 16 + 2 * q),     qs2);
            __half2 x1 = __hmul2(*(const __half2*)(Q1 + kc * 16 + 2 * q),     qs2);
            __half2 x2 = __hmul2(*(const __half2*)(Q0 + kc * 16 + 2 * q + 8), qs2);
            __half2 x3 = __hmul2(*(const __half2*)(Q1 + kc * 16 + 2 * q + 8), qs2);
            Qf[kc][0] = *(uint32_t*)&x0;
            Qf[kc][1] = *(uint32_t*)&x1;
            Qf[kc][2] = *(uint32_t*)&x2;
            Qf[kc][3] = *(uint32_t*)&x3;
        }
    }

    float O[8][4];
#pragma unroll
    for (int nb = 0; nb < 8; nb++)
#pragma unroll
        for (int i = 0; i < 4; i++) O[nb][i] = 0.f;
    float m0 = -INFINITY, m1 = -INFINITY, l0 = 0.f, l1 = 0.f;

    // ---- prologue: async-load tiles 0 and 1 ----
    load_tile(0);
    load_tile(1);

#pragma unroll 1
    for (int it = 0; it < NS / 64; it++) {
        const int cur = it % 3;
        if (it < NS / 64 - 1) { CP_WAIT1(); } else { CP_WAIT0(); }
        __syncthreads();   // tile `it` visible; readers of buf (it-1)%3 done
        const int any = (int)((mbits >> it) & 1u);
        if (it + 2 < NS / 64) load_tile(it + 2);

        const __half* Kcur = Ksm + cur * AT_TILE;
        const __half* Vcur = Vsm + cur * AT_TILE;

        // ---- QK^T via ldmatrix(non-trans) B-frags ----
        float D[8][4];
#pragma unroll
        for (int nb = 0; nb < 8; nb++) {
            D[nb][0] = 0.f; D[nb][1] = 0.f; D[nb][2] = 0.f; D[nb][3] = 0.f;
        }
#pragma unroll
        for (int kc = 0; kc < 4; kc++) {
#pragma unroll
            for (int nbp = 0; nbp < 4; nbp++) {
                int row = nbp * 16 + ((lane >> 4) & 1) * 8 + (lane & 7);
                int col = kc * 16 + ((lane >> 3) & 1) * 8;
                uint32_t bf[4];
                ldsm4(bf, cvta_s(Kcur + row * 72 + col));
                mma_f16(D[2 * nbp],     Qf[kc], bf[0], bf[1]);
                mma_f16(D[2 * nbp + 1], Qf[kc], bf[2], bf[3]);
            }
        }

        // ---- mask (rare path: read mask bytes from gmem) ----
        if (any) {
            const unsigned char* Msk = mp + it * 64;
#pragma unroll
            for (int nb = 0; nb < 8; nb++) {
                int c0 = nb * 8 + 2 * q;
                if (Msk[c0])     { D[nb][0] = -INFINITY; D[nb][2] = -INFINITY; }
                if (Msk[c0 + 1]) { D[nb][1] = -INFINITY; D[nb][3] = -INFINITY; }
            }
        }

        // ---- online softmax (log2 domain); rows g, g+8 ----
        float ml0 = -INFINITY, ml1 = -INFINITY;
#pragma unroll
        for (int nb = 0; nb < 8; nb++) {
            ml0 = fmaxf(ml0, fmaxf(D[nb][0], D[nb][1]));
            ml1 = fmaxf(ml1, fmaxf(D[nb][2], D[nb][3]));
        }
        ml0 = fmaxf(ml0, __shfl_xor_sync(0xffffffffu, ml0, 1));
        ml0 = fmaxf(ml0, __shfl_xor_sync(0xffffffffu, ml0, 2));
        ml1 = fmaxf(ml1, __shfl_xor_sync(0xffffffffu, ml1, 1));
        ml1 = fmaxf(ml1, __shfl_xor_sync(0xffffffffu, ml1, 2));

        float mn0 = fmaxf(m0, ml0), mn1 = fmaxf(m1, ml1);
        float ms0 = (mn0 == -INFINITY) ? 0.f : mn0;
        float ms1 = (mn1 == -INFINITY) ? 0.f : mn1;
#pragma unroll
        for (int nb = 0; nb < 8; nb++) {
            D[nb][0] = ex2f(D[nb][0] - ms0);
            D[nb][1] = ex2f(D[nb][1] - ms0);
            D[nb][2] = ex2f(D[nb][2] - ms1);
            D[nb][3] = ex2f(D[nb][3] - ms1);
        }

        float f0 = ex2f(m0 - ms0);   // exact 1.0 when max unchanged
        float f1 = ex2f(m1 - ms1);
        if (ml0 > m0 || ml1 > m1) {  // rescale only when a max moved
#pragma unroll
            for (int nb = 0; nb < 8; nb++) {
                O[nb][0] *= f0; O[nb][1] *= f0;
                O[nb][2] *= f1; O[nb][3] *= f1;
            }
        }
        m0 = mn0; m1 = mn1;

        // ---- O += P @ V ; row sums via P @ ones ----
        float Ssum[4] = {0.f, 0.f, 0.f, 0.f};
#pragma unroll
        for (int kk = 0; kk < 4; kk++) {
            uint32_t a[4];
            a[0] = packh2(D[2 * kk][0],     D[2 * kk][1]);
            a[1] = packh2(D[2 * kk][2],     D[2 * kk][3]);
            a[2] = packh2(D[2 * kk + 1][0], D[2 * kk + 1][1]);
            a[3] = packh2(D[2 * kk + 1][2], D[2 * kk + 1][3]);
            mma_f16(Ssum, a, ONES, ONES);
#pragma unroll
            for (int nbp = 0; nbp < 4; nbp++) {
                int row = kk * 16 + ((lane >> 3) & 1) * 8 + (lane & 7);
                int col = nbp * 16 + ((lane >> 4) & 1) * 8;
                uint32_t bf[4];
                ldsm4t(bf, cvta_s(Vcur + row * 72 + col));
                mma_f16(O[2 * nbp],     a, bf[0], bf[1]);
                mma_f16(O[2 * nbp + 1], a, bf[2], bf[3]);
            }
        }
        l0 = l0 * f0 + Ssum[0];
        l1 = l1 * f1 + Ssum[2];
        // no trailing barrier: next iteration's __syncthreads covers it
    }

    // ---- epilogue: normalize, write plain fp16 at [B*T, D] ----
    {
        float inv0 = (l0 > 0.f) ? (1.0f / l0) : 0.f;
        float inv1 = (l1 > 0.f) ? (1.0f / l1) : 0.f;
        size_t r0 = ((size_t)(b * NT + t0 + w16 + g))     * ND + h * NHD;
        size_t r1 = ((size_t)(b * NT + t0 + w16 + g + 8)) * ND + h * NHD;
#pragma unroll
        for (int nb = 0; nb < 8; nb++) {
            int c = nb * 8 + 2 * q;
            *(__half2*)&outh[r0 + c] =
                __floats2half2_rn(O[nb][0] * inv0, O[nb][1] * inv0);
            *(__half2*)&outh[r1 + c] =
                __floats2half2_rn(O[nb][2] * inv1, O[nb][3] * inv1);
        }
    }
}

// ---------------------------------------------------------------------------
extern "C" void kernel_launch(void* const* d_in, const int* in_sizes, int n_in,
                              void* d_out, int out_size)
{
    const float* query = (const float*)d_in[0];
    const float* key   = (const float*)d_in[1];
    const float* value = (const float*)d_in[2];
    const unsigned char* mask = (const unsigned char*)d_in[3];
    const float* Wq = (const float*)d_in[4];
    const float* bq = (const float*)d_in[5];
    const float* Wk = (const float*)d_in[6];
    const float* bk = (const float*)d_in[7];
    const float* Wv = (const float*)d_in[8];
    const float* bv = (const float*)d_in[9];
    const float* Wo = (const float*)d_in[10];
    const float* bo = (const float*)d_in[11];
    float* out = (float*)d_out;

    __half *qb, *kb, *vb, *ah, *al, *wh, *wl, *oh;
    cudaGetSymbolAddress((void**)&qb, g_q);
    cudaGetSymbolAddress((void**)&kb, g_k);
    cudaGetSymbolAddress((void**)&vb, g_v);
    cudaGetSymbolAddress((void**)&ah, g_ah);
    cudaGetSymbolAddress((void**)&al, g_al);
    cudaGetSymbolAddress((void**)&wh, g_wh);
    cudaGetSymbolAddress((void**)&wl, g_wl);
    cudaGetSymbolAddress((void**)&oh, g_oh);

    const int smem3 = G2_ST * 2 * (int)sizeof(__half);   // 61440 B
    cudaFuncSetAttribute(gemmqkv_kernel,
                         cudaFuncAttributeMaxDynamicSharedMemorySize, smem3);
    cudaFuncSetAttribute(gemmwo_kernel,
                         cudaFuncAttributeMaxDynamicSharedMemorySize, smem3);
    cudaFuncSetAttribute(attn_kernel,
                         cudaFuncAttributeMaxDynamicSharedMemorySize, AT_SMEM);

    const int NW = ND * ND;               // 262144 per weight
    const int NA = NB * NT * ND;          // 8388608 per activation

    // fused splits: one launch for 4 weights, one for 3 activations
    split4_kernel<<<dim3(NW / 1024, 4), 256>>>(Wq, Wk, Wv, Wo, wh, wl, NW);
    split4_kernel<<<dim3(NA / 1024, 3), 256>>>(query, key, value, query,
                                               ah, al, NA);

    // fused QKV projections (one launch, grid.z selects projection)
    dim3 gq(ND / 64, (NB * NT) / 128, 3);   // (8, 128, 3)
    gemmqkv_kernel<<<gq, 256, smem3>>>(ah, al, wh, wl, bq, bk, bv, qb, kb, vb);

    dim3 ga(NT / 64, NH, NB);               // (64, 8, 4)
    attn_kernel<<<ga, 128, AT_SMEM>>>(qb, kb, vb, mask, oh);

    dim3 gg(ND / 64, (NB * NT) / 128);      // (8, 128)
    gemmwo_kernel<<<gg, 256, smem3>>>(oh, wh + 3 * NW, wl + 3 * NW, bo, out);
}

// round 14
// speedup vs baseline: 1.7405x; 1.2991x over previous
#include <cuda_runtime.h>
#include <cuda_fp16.h>
#include <math.h>
#include <stdint.h>

#define NB 4
#define NT 4096
#define NS 4096
#define ND 512
#define NH 8
#define NHD 64

// Scratch (allocation-free rule: __device__ globals)
__device__ __half g_q[NB * NH * NT * NHD];
__device__ __half g_k[NB * NH * NS * NHD];
__device__ __half g_v[NB * NH * NS * NHD];
__device__ __half g_ah[3 * NB * NT * ND];   // hi split of query|key|value
__device__ __half g_wh[4 * ND * ND];        // hi split of Wq|Wk|Wv|Wo
__device__ __half g_wl[4 * ND * ND];
__device__ __half g_oh[NB * NT * ND];       // attention output (fp16)

// ===========================================================================
// helpers
// ===========================================================================
__device__ __forceinline__ float ex2f(float x) {
    float y;
    asm("ex2.approx.ftz.f32 %0, %1;" : "=f"(y) : "f"(x));
    return y;
}
__device__ __forceinline__ uint32_t packh2(float lo, float hi) {
    __half2 h = __floats2half2_rn(lo, hi);
    return *reinterpret_cast<uint32_t*>(&h);
}
__device__ __forceinline__ uint32_t cvta_s(const void* p) {
    return (uint32_t)__cvta_generic_to_shared(p);
}
// D += A * B  (m16n8k16 fp16 in, fp32 accum; A row-major, B col-major)
__device__ __forceinline__ void mma_f16(float* d, const uint32_t* a,
                                        uint32_t b0, uint32_t b1) {
    asm volatile(
        "mma.sync.aligned.m16n8k16.row.col.f32.f16.f16.f32 "
        "{%0,%1,%2,%3}, {%4,%5,%6,%7}, {%8,%9}, {%0,%1,%2,%3};"
        : "+f"(d[0]), "+f"(d[1]), "+f"(d[2]), "+f"(d[3])
        : "r"(a[0]), "r"(a[1]), "r"(a[2]), "r"(a[3]), "r"(b0), "r"(b1));
}
__device__ __forceinline__ void ldsm4(uint32_t* r, uint32_t addr) {
    asm volatile("ldmatrix.sync.aligned.m8n8.x4.shared.b16 {%0,%1,%2,%3}, [%4];"
                 : "=r"(r[0]), "=r"(r[1]), "=r"(r[2]), "=r"(r[3]) : "r"(addr));
}
__device__ __forceinline__ void ldsm4t(uint32_t* r, uint32_t addr) {
    asm volatile("ldmatrix.sync.aligned.m8n8.x4.trans.shared.b16 {%0,%1,%2,%3}, [%4];"
                 : "=r"(r[0]), "=r"(r[1]), "=r"(r[2]), "=r"(r[3]) : "r"(addr));
}
__device__ __forceinline__ void cp16(uint32_t dst, const void* src) {
    asm volatile("cp.async.cg.shared.global [%0], [%1], 16;" :: "r"(dst), "l"(src));
}
#define CP_COMMIT() asm volatile("cp.async.commit_group;")
#define CP_WAIT1()  asm volatile("cp.async.wait_group 1;")
#define CP_WAIT0()  asm volatile("cp.async.wait_group 0;")

// ---------------------------------------------------------------------------
// fused split: fp32 -> hi fp16 (+ optional lo); blockIdx.y selects tensor
// ---------------------------------------------------------------------------
__global__ __launch_bounds__(256)
void split4_kernel(const float* __restrict__ i0, const float* __restrict__ i1,
                   const float* __restrict__ i2, const float* __restrict__ i3,
                   __half* __restrict__ hi, __half* __restrict__ lo, int n)
{
    const float* in = (blockIdx.y == 0) ? i0 : (blockIdx.y == 1) ? i1
                    : (blockIdx.y == 2) ? i2 : i3;
    const size_t off = (size_t)blockIdx.y * n;
    int i = (blockIdx.x * 256 + threadIdx.x) * 4;
    if (i >= n) return;
    float4 v = *(const float4*)(in + i);
    __half h[4];
    h[0] = __float2half_rn(v.x);
    h[1] = __float2half_rn(v.y);
    h[2] = __float2half_rn(v.z);
    h[3] = __float2half_rn(v.w);
    *(uint2*)(hi + off + i) = *(uint2*)h;
    if (lo) {
        __half l[4];
        l[0] = __float2half_rn(v.x - __half2float(h[0]));
        l[1] = __float2half_rn(v.y - __half2float(h[1]));
        l[2] = __float2half_rn(v.z - __half2float(h[2]));
        l[3] = __float2half_rn(v.w - __half2float(h[3]));
        *(uint2*)(lo + off + i) = *(uint2*)l;
    }
}

// ---------------------------------------------------------------------------
// split-fp16 GEMM core (R10 schedule, proven). 2-term: Ah*Wh + Ah*Wl
// (A plain fp16; W split keeps weights fp32-accurate).
// ---------------------------------------------------------------------------
#define G2_AH 0                       // offsets in halves within a stage
#define G2_WH (128 * 40)
#define G2_WL (128 * 40 + 64 * 40)
#define G2_ST (128 * 40 + 2 * 64 * 40)   // 10240 halves per stage

__device__ __forceinline__
void gemm2_body(const __half* Ah, const __half* Wh, const __half* Wl,
                const float* bias, void* outp, int head_layout)
{
    extern __shared__ __half dsm[];

    const int tid  = threadIdx.x;
    const int warp = tid >> 5, lane = tid & 31;
    const int g = lane >> 2, q = lane & 3;
    const int m0 = blockIdx.y * 128;
    const int n0 = blockIdx.x * 64;

    const int arow = tid >> 1, acb = (tid & 1) * 16;
    const int wrow = tid >> 2, wcb = (tid & 3) * 8;

    const __half* Agh = Ah + (size_t)(m0 + arow) * ND + acb;
    const __half* Wgh = Wh + (size_t)(n0 + wrow) * ND + wcb;
    const __half* Wgl = Wl + (size_t)(n0 + wrow) * ND + wcb;

    float D[8][4];
#pragma unroll
    for (int nb = 0; nb < 8; nb++)
#pragma unroll
        for (int i = 0; i < 4; i++) D[nb][i] = 0.f;

    auto load_stage = [&](int stage, int k0) {
        __half* base = dsm + (stage & 1) * G2_ST;
        uint32_t ah = cvta_s(base + G2_AH + arow * 40 + acb);
        uint32_t wh = cvta_s(base + G2_WH + wrow * 40 + wcb);
        uint32_t wl = cvta_s(base + G2_WL + wrow * 40 + wcb);
#pragma unroll
        for (int j = 0; j < 2; j++)
            cp16(ah + j * 16, Agh + k0 + j * 8);
        cp16(wh, Wgh + k0);
        cp16(wl, Wgl + k0);
        CP_COMMIT();
    };

    load_stage(0, 0);
    load_stage(1, 32);

#pragma unroll 1
    for (int it = 0; it < ND / 32; it++) {
        const __half* base = dsm + (it & 1) * G2_ST;

        if (it < ND / 32 - 1) { CP_WAIT1(); } else { CP_WAIT0(); }
        __syncthreads();

#pragma unroll
        for (int kc = 0; kc < 2; kc++) {
            int arw = warp * 16 + (lane & 15);
            int acl = kc * 16 + (lane >> 4) * 8;
            uint32_t ahf[4];
            ldsm4(ahf, cvta_s(base + G2_AH + arw * 40 + acl));
#pragma unroll
            for (int nbp = 0; nbp < 4; nbp++) {
                int row = nbp * 16 + ((lane >> 4) & 1) * 8 + (lane & 7);
                int col = kc * 16 + ((lane >> 3) & 1) * 8;
                uint32_t bh[4], bl[4];
                ldsm4(bh, cvta_s(base + G2_WH + row * 40 + col));
                ldsm4(bl, cvta_s(base + G2_WL + row * 40 + col));
                mma_f16(D[2 * nbp],     ahf, bh[0], bh[1]);
                mma_f16(D[2 * nbp + 1], ahf, bh[2], bh[3]);
                mma_f16(D[2 * nbp],     ahf, bl[0], bl[1]);
                mma_f16(D[2 * nbp + 1], ahf, bl[2], bl[3]);
            }
        }
        __syncthreads();
        if (it + 2 < ND / 32) load_stage(it + 2, (it + 2) * 32);
    }

    // ---- epilogue ----
    const float* bp = bias + n0;
    const int mg = m0 + warp * 16 + g;
#pragma unroll
    for (int nb = 0; nb < 8; nb++) {
        int c = nb * 8 + 2 * q;
        float2 bb = *(const float2*)(bp + c);
        float o00 = D[nb][0] + bb.x, o01 = D[nb][1] + bb.y;   // row mg
        float o10 = D[nb][2] + bb.x, o11 = D[nb][3] + bb.y;   // row mg+8
        if (head_layout) {
            int h = n0 >> 6;
            int bbi = mg >> 12, t = mg & 4095;
            __half* oh = (__half*)outp;
            size_t bse = ((size_t)(bbi * NH + h) * NT + t) * NHD + c;
            *(__half2*)&oh[bse]           = __floats2half2_rn(o00, o01);
            *(__half2*)&oh[bse + 8 * NHD] = __floats2half2_rn(o10, o11);
        } else {
            float* of = (float*)outp;
            size_t bse = (size_t)mg * ND + n0 + c;
            *(float2*)&of[bse]          = make_float2(o00, o01);
            *(float2*)&of[bse + 8 * ND] = make_float2(o10, o11);
        }
    }
}

// fused QKV projections: blockIdx.z selects (activation, weight, bias, out)
__global__ __launch_bounds__(256, 3)
void gemmqkv_kernel(const __half* __restrict__ ah,
                    const __half* __restrict__ wh, const __half* __restrict__ wl,
                    const float* __restrict__ bq, const float* __restrict__ bk,
                    const float* __restrict__ bv,
                    __half* __restrict__ qb, __half* __restrict__ kb,
                    __half* __restrict__ vb)
{
    const int z = blockIdx.z;
    const size_t NAo = (size_t)NB * NT * ND;
    const size_t NWo = (size_t)ND * ND;
    const float* bias = (z == 0) ? bq : (z == 1) ? bk : bv;
    __half* outp = (z == 0) ? qb : (z == 1) ? kb : vb;
    gemm2_body(ah + z * NAo, wh + z * NWo, wl + z * NWo, bias, outp, 1);
}

// Wo projection: A is plain fp16 (attention output), fp32 out
__global__ __launch_bounds__(256, 3)
void gemmwo_kernel(const __half* __restrict__ Ah,
                   const __half* __restrict__ Wh, const __half* __restrict__ Wl,
                   const float* __restrict__ bias, float* __restrict__ outp)
{
    gemm2_body(Ah, Wh, Wl, bias, outp, 0);
}

// ---------------------------------------------------------------------------
// fp16 flash attention v9: T-tile 128 (256 thr / 8 warps, 16 rows/warp),
// 3-stage ring-buffered K/V, one barrier per tile, per-CTA 64-bit tile mask
// bitmask, fp32 ex2, fp16 output. Halves KV L2/gmem traffic + barrier
// overhead per unit work vs v8.
// ---------------------------------------------------------------------------
#define AT_TILE (64 * 72)                 // halves per K or V buffer
#define AT_SMEM (6 * AT_TILE * 2)         // bytes: 55296

__global__ __launch_bounds__(256)
void attn_kernel(const __half* __restrict__ Qh, const __half* __restrict__ Kh,
                 const __half* __restrict__ Vh,
                 const unsigned char* __restrict__ mask,
                 __half* __restrict__ outh)
{
    extern __shared__ __half asmem[];
    __half* Ksm = asmem;                 // [3][64][72]
    __half* Vsm = asmem + 3 * AT_TILE;   // [3][64][72]

    const int b  = blockIdx.z;
    const int h  = blockIdx.y;
    const int t0 = blockIdx.x * 128;
    const int tid  = threadIdx.x;
    const int warp = tid >> 5;
    const int lane = tid & 31;
    const int g = lane >> 2;
    const int q = lane & 3;
    const int w16 = warp * 16;
    const uint32_t ONES = 0x3C003C00u;   // half2(1,1)

    const __half* Kp = Kh + (size_t)(b * NH + h) * NS * NHD;
    const __half* Vp = Vh + (size_t)(b * NH + h) * NS * NHD;
    const unsigned char* mp = mask + (size_t)b * NS;

    const int lrow = tid >> 2;           // 0..63 (4 threads per s-row)
    const int lcol = (tid & 3) * 16;     // 0,16,32,48 (halves)

    auto load_tile = [&](int t) {
        int buf = t % 3;
        const __half* kg = Kp + (size_t)(t * 64 + lrow) * NHD + lcol;
        const __half* vg = Vp + (size_t)(t * 64 + lrow) * NHD + lcol;
        uint32_t kd = cvta_s(Ksm + buf * AT_TILE + lrow * 72 + lcol);
        uint32_t vd = cvta_s(Vsm + buf * AT_TILE + lrow * 72 + lcol);
#pragma unroll
        for (int j = 0; j < 2; j++) {
            cp16(kd + j * 16, kg + j * 8);
            cp16(vd + j * 16, vg + j * 8);
        }
        CP_COMMIT();
    };

    // ---- per-CTA 64-bit "tile has masked column" bitmask (computed once) ---
    uint64_t mbits;
    {
        const uint4* mq = (const uint4*)mp;          // 4096 B = 256 uint4
        uint4 a = mq[tid];                           // 16 B per thread
        uint32_t o = a.x | a.y | a.z | a.w;
        uint32_t bal = __ballot_sync(0xffffffffu, o != 0u);
        uint32_t t8 = 0;
#pragma unroll
        for (int j = 0; j < 8; j++)
            t8 |= (((bal >> (4 * j)) & 0xFu) ? 1u : 0u) << j;
        __shared__ uint32_t wbits[8];
        if (lane == 0) wbits[warp] = t8;
        __syncthreads();
        mbits = 0;
#pragma unroll
        for (int w = 0; w < 8; w++)
            mbits |= (uint64_t)wbits[w] << (8 * w);
    }

    // ---- Q fragments (fp16 regs, once), scale 0.125*log2(e) ----
    uint32_t Qf[4][4];
    {
        const __half2 qs2 = __float2half2_rn(0.125f * 1.4426950408889634f);
        const __half* Q0 = Qh + ((size_t)(b * NH + h) * NT + t0 + w16 + g) * NHD;
        const __half* Q1 = Q0 + 8 * NHD;
#pragma unroll
        for (int kc = 0; kc < 4; kc++) {
            __half2 x0 = __hmul2(*(const __half2*)(Q0 + kc * 16 + 2 * q),     qs2);
            __half2 x1 = __hmul2(*(const __half2*)(Q1 + kc * 16 + 2 * q),     qs2);
            __half2 x2 = __hmul2(*(const __half2*)(Q0 + kc * 16 + 2 * q + 8), qs2);
            __half2 x3 = __hmul2(*(const __half2*)(Q1 + kc * 16 + 2 * q + 8), qs2);
            Qf[kc][0] = *(uint32_t*)&x0;
            Qf[kc][1] = *(uint32_t*)&x1;
            Qf[kc][2] = *(uint32_t*)&x2;
            Qf[kc][3] = *(uint32_t*)&x3;
        }
    }

    float O[8][4];
#pragma unroll
    for (int nb = 0; nb < 8; nb++)
#pragma unroll
        for (int i = 0; i < 4; i++) O[nb][i] = 0.f;
    float m0 = -INFINITY, m1 = -INFINITY, l0 = 0.f, l1 = 0.f;

    // ---- prologue: async-load tiles 0 and 1 ----
    load_tile(0);
    load_tile(1);

#pragma unroll 1
    for (int it = 0; it < NS / 64; it++) {
        const int cur = it % 3;
        if (it < NS / 64 - 1) { CP_WAIT1(); } else { CP_WAIT0(); }
        __syncthreads();   // tile `it` visible; readers of buf (it-1)%3 done
        const int any = (int)((mbits >> it) & 1u);
        if (it + 2 < NS / 64) load_tile(it + 2);

        const __half* Kcur = Ksm + cur * AT_TILE;
        const __half* Vcur = Vsm + cur * AT_TILE;

        // ---- QK^T via ldmatrix(non-trans) B-frags ----
        float D[8][4];
#pragma unroll
        for (int nb = 0; nb < 8; nb++) {
            D[nb][0] = 0.f; D[nb][1] = 0.f; D[nb][2] = 0.f; D[nb][3] = 0.f;
        }
#pragma unroll
        for (int kc = 0; kc < 4; kc++) {
#pragma unroll
            for (int nbp = 0; nbp < 4; nbp++) {
                int row = nbp * 16 + ((lane >> 4) & 1) * 8 + (lane & 7);
                int col = kc * 16 + ((lane >> 3) & 1) * 8;
                uint32_t bf[4];
                ldsm4(bf, cvta_s(Kcur + row * 72 + col));
                mma_f16(D[2 * nbp],     Qf[kc], bf[0], bf[1]);
                mma_f16(D[2 * nbp + 1], Qf[kc], bf[2], bf[3]);
            }
        }

        // ---- mask (rare path: read mask bytes from gmem) ----
        if (any) {
            const unsigned char* Msk = mp + it * 64;
#pragma unroll
            for (int nb = 0; nb < 8; nb++) {
                int c0 = nb * 8 + 2 * q;
                if (Msk[c0])     { D[nb][0] = -INFINITY; D[nb][2] = -INFINITY; }
                if (Msk[c0 + 1]) { D[nb][1] = -INFINITY; D[nb][3] = -INFINITY; }
            }
        }

        // ---- online softmax (log2 domain); rows g, g+8 ----
        float ml0 = -INFINITY, ml1 = -INFINITY;
#pragma unroll
        for (int nb = 0; nb < 8; nb++) {
            ml0 = fmaxf(ml0, fmaxf(D[nb][0], D[nb][1]));
            ml1 = fmaxf(ml1, fmaxf(D[nb][2], D[nb][3]));
        }
        ml0 = fmaxf(ml0, __shfl_xor_sync(0xffffffffu, ml0, 1));
        ml0 = fmaxf(ml0, __shfl_xor_sync(0xffffffffu, ml0, 2));
        ml1 = fmaxf(ml1, __shfl_xor_sync(0xffffffffu, ml1, 1));
        ml1 = fmaxf(ml1, __shfl_xor_sync(0xffffffffu, ml1, 2));

        float mn0 = fmaxf(m0, ml0), mn1 = fmaxf(m1, ml1);
        float ms0 = (mn0 == -INFINITY) ? 0.f : mn0;
        float ms1 = (mn1 == -INFINITY) ? 0.f : mn1;
#pragma unroll
        for (int nb = 0; nb < 8; nb++) {
            D[nb][0] = ex2f(D[nb][0] - ms0);
            D[nb][1] = ex2f(D[nb][1] - ms0);
            D[nb][2] = ex2f(D[nb][2] - ms1);
            D[nb][3] = ex2f(D[nb][3] - ms1);
        }

        float f0 = ex2f(m0 - ms0);   // exact 1.0 when max unchanged
        float f1 = ex2f(m1 - ms1);
        if (ml0 > m0 || ml1 > m1) {  // rescale only when a max moved
#pragma unroll
            for (int nb = 0; nb < 8; nb++) {
                O[nb][0] *= f0; O[nb][1] *= f0;
                O[nb][2] *= f1; O[nb][3] *= f1;
            }
        }
        m0 = mn0; m1 = mn1;

        // ---- O += P @ V ; row sums via P @ ones ----
        float Ssum[4] = {0.f, 0.f, 0.f, 0.f};
#pragma unroll
        for (int kk = 0; kk < 4; kk++) {
            uint32_t a[4];
            a[0] = packh2(D[2 * kk][0],     D[2 * kk][1]);
            a[1] = packh2(D[2 * kk][2],     D[2 * kk][3]);
            a[2] = packh2(D[2 * kk + 1][0], D[2 * kk + 1][1]);
            a[3] = packh2(D[2 * kk + 1][2], D[2 * kk + 1][3]);
            mma_f16(Ssum, a, ONES, ONES);
#pragma unroll
            for (int nbp = 0; nbp < 4; nbp++) {
                int row = kk * 16 + ((lane >> 3) & 1) * 8 + (lane & 7);
                int col = nbp * 16 + ((lane >> 4) & 1) * 8;
                uint32_t bf[4];
                ldsm4t(bf, cvta_s(Vcur + row * 72 + col));
                mma_f16(O[2 * nbp],     a, bf[0], bf[1]);
                mma_f16(O[2 * nbp + 1], a, bf[2], bf[3]);
            }
        }
        l0 = l0 * f0 + Ssum[0];
        l1 = l1 * f1 + Ssum[2];
        // no trailing barrier: next iteration's __syncthreads covers it
    }

    // ---- epilogue: normalize, write plain fp16 at [B*T, D] ----
    {
        float inv0 = (l0 > 0.f) ? (1.0f / l0) : 0.f;
        float inv1 = (l1 > 0.f) ? (1.0f / l1) : 0.f;
        size_t r0 = ((size_t)(b * NT + t0 + w16 + g))     * ND + h * NHD;
        size_t r1 = ((size_t)(b * NT + t0 + w16 + g + 8)) * ND + h * NHD;
#pragma unroll
        for (int nb = 0; nb < 8; nb++) {
            int c = nb * 8 + 2 * q;
            *(__half2*)&outh[r0 + c] =
                __floats2half2_rn(O[nb][0] * inv0, O[nb][1] * inv0);
            *(__half2*)&outh[r1 + c] =
                __floats2half2_rn(O[nb][2] * inv1, O[nb][3] * inv1);
        }
    }
}

// ---------------------------------------------------------------------------
extern "C" void kernel_launch(void* const* d_in, const int* in_sizes, int n_in,
                              void* d_out, int out_size)
{
    const float* query = (const float*)d_in[0];
    const float* key   = (const float*)d_in[1];
    const float* value = (const float*)d_in[2];
    const unsigned char* mask = (const unsigned char*)d_in[3];
    const float* Wq = (const float*)d_in[4];
    const float* bq = (const float*)d_in[5];
    const float* Wk = (const float*)d_in[6];
    const float* bk = (const float*)d_in[7];
    const float* Wv = (const float*)d_in[8];
    const float* bv = (const float*)d_in[9];
    const float* Wo = (const float*)d_in[10];
    const float* bo = (const float*)d_in[11];
    float* out = (float*)d_out;

    __half *qb, *kb, *vb, *ah, *wh, *wl, *oh;
    cudaGetSymbolAddress((void**)&qb, g_q);
    cudaGetSymbolAddress((void**)&kb, g_k);
    cudaGetSymbolAddress((void**)&vb, g_v);
    cudaGetSymbolAddress((void**)&ah, g_ah);
    cudaGetSymbolAddress((void**)&wh, g_wh);
    cudaGetSymbolAddress((void**)&wl, g_wl);
    cudaGetSymbolAddress((void**)&oh, g_oh);

    const int smem2 = G2_ST * 2 * (int)sizeof(__half);   // 40960 B
    cudaFuncSetAttribute(gemmqkv_kernel,
                         cudaFuncAttributeMaxDynamicSharedMemorySize, smem2);
    cudaFuncSetAttribute(gemmwo_kernel,
                         cudaFuncAttributeMaxDynamicSharedMemorySize, smem2);
    cudaFuncSetAttribute(attn_kernel,
                         cudaFuncAttributeMaxDynamicSharedMemorySize, AT_SMEM);

    const int NW = ND * ND;               // 262144 per weight
    const int NA = NB * NT * ND;          // 8388608 per activation

    // fused splits: weights get hi+lo; activations hi only
    split4_kernel<<<dim3(NW / 1024, 4), 256>>>(Wq, Wk, Wv, Wo, wh, wl, NW);
    split4_kernel<<<dim3(NA / 1024, 3), 256>>>(query, key, value, query,
                                               ah, (/*no lo*/ __half*)nullptr, NA);

    // fused QKV projections (one launch, grid.z selects projection)
    dim3 gq(ND / 64, (NB * NT) / 128, 3);   // (8, 128, 3)
    gemmqkv_kernel<<<gq, 256, smem2>>>(ah, wh, wl, bq, bk, bv, qb, kb, vb);

    dim3 ga(NT / 128, NH, NB);              // (32, 8, 4)
    attn_kernel<<<ga, 256, AT_SMEM>>>(qb, kb, vb, mask, oh);

    dim3 gg(ND / 64, (NB * NT) / 128);      // (8, 128)
    gemmwo_kernel<<<gg, 256, smem2>>>(oh, wh + 3 * NW, wl + 3 * NW, bo, out);
}